// round 11
// baseline (speedup 1.0000x reference)
#include <cuda_runtime.h>
#include <math.h>

// Problem constants
#define TT 26
#define NB 2
#define NT (NB*TT)      // 52 frames
#define CC 256
#define HW 256          // 16*16
#define NHEAD 8
#define CPH 32          // C / NHEAD

// ---------------------------------------------------------------------------
// Fast exp on the FMA pipe (no MUFU). Input x <= 0 (softmax deltas).
// exp(x) = 2^y, y = x*log2e; n = round(y), r = y-n in [-0.5,0.5];
// 2^r via degree-5 Taylor (rel err ~2e-6); scale by 2^n via exponent bits.
// ---------------------------------------------------------------------------
__device__ __forceinline__ float fast_exp(float x) {
    float y = fmaxf(x, -87.0f) * 1.4426950408889634f;
    float fn = y + 12582912.0f;                 // 1.5 * 2^23 magic round
    int n = __float_as_int(fn) - 0x4B400000;
    float r = y - (fn - 12582912.0f);           // [-0.5, 0.5]
    float p = 1.3333558146e-3f;
    p = fmaf(p, r, 9.6181291794e-3f);
    p = fmaf(p, r, 5.5504108664e-2f);
    p = fmaf(p, r, 2.4022650696e-1f);
    p = fmaf(p, r, 6.9314718056e-1f);
    p = fmaf(p, r, 1.0f);
    return p * __int_as_float((n + 127) << 23);
}

// ---------------------------------------------------------------------------
// init_out: out[n][oc][hw] = b_out[oc]  (also clears the 0xAA poison)
// ---------------------------------------------------------------------------
__global__ __launch_bounds__(256, 1)
void init_out(const float* __restrict__ b_out, float* __restrict__ out, int total)
{
    int i = blockIdx.x * blockDim.x + threadIdx.x;
    if (i < total) out[i] = b_out[(i >> 8) & 255];
}

// ---------------------------------------------------------------------------
// Fused attention + output projection. One block per (frame n, head).
// 512 threads = 2 threads per query (each owns 16 of 32 channels).
// Smem rows padded to 36 floats (144 B) so all hot-loop accesses are
// 16B-aligned float4 (4x fewer LDS/STS instructions vs scalar).
// ---------------------------------------------------------------------------
__global__ __launch_bounds__(512, 1)
void attn_fused(const float* __restrict__ x,
                const float* __restrict__ w_qkv,
                const float* __restrict__ b_qkv,
                const float* __restrict__ w_out,
                const int* __restrict__ access,
                float* __restrict__ out)
{
    // Layout (floats):
    //   Ks [128][36] @ 0     (4608)
    //   Vs [128][36] @ 4608  (4608)
    //   Wk [32][32]  @ 9216  (1024)
    //   Wv [32][32]  @ 10240 (1024)
    //   Epilogue overlays woT[256][32] (8192) @ 0.
    __shared__ __align__(16) float sm[11264];
    float* Ks = sm;
    float* Vs = sm + 4608;
    float* Wk = sm + 9216;
    float* Wv = sm + 10240;

    const int tid   = threadIdx.x;
    const int query = tid >> 1;           // 0..255 (= hw)
    const int half  = tid & 1;
    const int qoff  = half * 16;          // channel group within the head
    const int bid   = blockIdx.x;
    const int n     = bid >> 3;           // global frame
    const int head  = bid & 7;
    const int t     = n % TT;
    const int b_    = n / TT;

    // ---- Phase A: recompute q[16] (chunked Wq staging through Wk) ----
    float q0=0.f,q1=0.f,q2=0.f,q3=0.f,q4=0.f,q5=0.f,q6=0.f,q7=0.f;
    float q8=0.f,q9=0.f,q10=0.f,q11=0.f,q12=0.f,q13=0.f,q14=0.f,q15=0.f;

    const float* xq = x + (size_t)n * (CC * HW) + query;
    for (int c0 = 0; c0 < 256; c0 += 32) {
        __syncthreads();
        {
            int idx = tid;                 // 0..511
            int ch = idx & 31, cc = idx >> 5;
            Wk[ch * 32 + cc] = w_qkv[(size_t)(cc * 8 + head) * CC + c0 + ch];
            idx = tid + 512;               // 512..1023
            ch = idx & 31; cc = idx >> 5;
            Wk[ch * 32 + cc] = w_qkv[(size_t)(cc * 8 + head) * CC + c0 + ch];
        }
        __syncthreads();
#pragma unroll 8
        for (int ch = 0; ch < 32; ch++) {
            float xv = xq[(size_t)(c0 + ch) * HW];
            const float4* wr = (const float4*)(Wk + ch * 32 + qoff);
            float4 w0 = wr[0], w1 = wr[1], w2 = wr[2], w3 = wr[3];
            q0  = fmaf(xv, w0.x, q0);  q1  = fmaf(xv, w0.y, q1);
            q2  = fmaf(xv, w0.z, q2);  q3  = fmaf(xv, w0.w, q3);
            q4  = fmaf(xv, w1.x, q4);  q5  = fmaf(xv, w1.y, q5);
            q6  = fmaf(xv, w1.z, q6);  q7  = fmaf(xv, w1.w, q7);
            q8  = fmaf(xv, w2.x, q8);  q9  = fmaf(xv, w2.y, q9);
            q10 = fmaf(xv, w2.z, q10); q11 = fmaf(xv, w2.w, q11);
            q12 = fmaf(xv, w3.x, q12); q13 = fmaf(xv, w3.y, q13);
            q14 = fmaf(xv, w3.z, q14); q15 = fmaf(xv, w3.w, q15);
        }
    }
    const float scale = 0.17677669529663687f;   // 1/sqrt(32)
    q0  = (q0  + b_qkv[(qoff+0)*8+head])  * scale;
    q1  = (q1  + b_qkv[(qoff+1)*8+head])  * scale;
    q2  = (q2  + b_qkv[(qoff+2)*8+head])  * scale;
    q3  = (q3  + b_qkv[(qoff+3)*8+head])  * scale;
    q4  = (q4  + b_qkv[(qoff+4)*8+head])  * scale;
    q5  = (q5  + b_qkv[(qoff+5)*8+head])  * scale;
    q6  = (q6  + b_qkv[(qoff+6)*8+head])  * scale;
    q7  = (q7  + b_qkv[(qoff+7)*8+head])  * scale;
    q8  = (q8  + b_qkv[(qoff+8)*8+head])  * scale;
    q9  = (q9  + b_qkv[(qoff+9)*8+head])  * scale;
    q10 = (q10 + b_qkv[(qoff+10)*8+head]) * scale;
    q11 = (q11 + b_qkv[(qoff+11)*8+head]) * scale;
    q12 = (q12 + b_qkv[(qoff+12)*8+head]) * scale;
    q13 = (q13 + b_qkv[(qoff+13)*8+head]) * scale;
    q14 = (q14 + b_qkv[(qoff+14)*8+head]) * scale;
    q15 = (q15 + b_qkv[(qoff+15)*8+head]) * scale;

    // ---- Online softmax over 4 gathered frames x 2 half-tiles of 128 keys ----
    float mx = -1e30f, l = 0.f;
    float a0=0.f,a1=0.f,a2=0.f,a3=0.f,a4=0.f,a5=0.f,a6=0.f,a7=0.f;
    float a8=0.f,a9=0.f,a10=0.f,a11=0.f,a12=0.f,a13=0.f,a14=0.f,a15=0.f;

    const int kk   = tid >> 2;            // key 0..127 (build mapping)
    const int coff = (tid & 3) * 8;       // channel group 0,8,16,24

    for (int tt = 0; tt < 8; tt++) {
        const int g  = tt >> 1;
        const int hf = tt & 1;
        const int f  = access[t * 4 + g];
        const int nf = b_ * TT + f;
        const float* xk = x + (size_t)nf * (CC * HW) + hf * 128 + kk;

        // -- build K/V tile: each thread accumulates 8 K-cols and 8 V-cols --
        float k0=0.f,k1=0.f,k2=0.f,k3=0.f,k4=0.f,k5=0.f,k6=0.f,k7=0.f;
        float v0=0.f,v1=0.f,v2=0.f,v3=0.f,v4=0.f,v5=0.f,v6=0.f,v7=0.f;
        for (int c0 = 0; c0 < 256; c0 += 32) {
            __syncthreads();
            {
                int idx = tid;
                int ch = idx & 31, cc = idx >> 5;
                Wk[ch*32+cc] = w_qkv[(size_t)(256 + cc*8 + head) * CC + c0 + ch];
                Wv[ch*32+cc] = w_qkv[(size_t)(512 + cc*8 + head) * CC + c0 + ch];
                idx = tid + 512;
                ch = idx & 31; cc = idx >> 5;
                Wk[ch*32+cc] = w_qkv[(size_t)(256 + cc*8 + head) * CC + c0 + ch];
                Wv[ch*32+cc] = w_qkv[(size_t)(512 + cc*8 + head) * CC + c0 + ch];
            }
            __syncthreads();
#pragma unroll 4
            for (int ch = 0; ch < 32; ch++) {
                float xv = xk[(size_t)(c0 + ch) * HW];
                const float4* wkr = (const float4*)(Wk + ch * 32 + coff);
                const float4* wvr = (const float4*)(Wv + ch * 32 + coff);
                float4 wk0 = wkr[0], wk1 = wkr[1];
                float4 wv0 = wvr[0], wv1 = wvr[1];
                k0 = fmaf(xv, wk0.x, k0); k1 = fmaf(xv, wk0.y, k1);
                k2 = fmaf(xv, wk0.z, k2); k3 = fmaf(xv, wk0.w, k3);
                k4 = fmaf(xv, wk1.x, k4); k5 = fmaf(xv, wk1.y, k5);
                k6 = fmaf(xv, wk1.z, k6); k7 = fmaf(xv, wk1.w, k7);
                v0 = fmaf(xv, wv0.x, v0); v1 = fmaf(xv, wv0.y, v1);
                v2 = fmaf(xv, wv0.z, v2); v3 = fmaf(xv, wv0.w, v3);
                v4 = fmaf(xv, wv1.x, v4); v5 = fmaf(xv, wv1.y, v5);
                v6 = fmaf(xv, wv1.z, v6); v7 = fmaf(xv, wv1.w, v7);
            }
        }
        {
            float4 s0, s1;
            s0.x = k0 + b_qkv[256 + (coff+0)*8 + head];
            s0.y = k1 + b_qkv[256 + (coff+1)*8 + head];
            s0.z = k2 + b_qkv[256 + (coff+2)*8 + head];
            s0.w = k3 + b_qkv[256 + (coff+3)*8 + head];
            s1.x = k4 + b_qkv[256 + (coff+4)*8 + head];
            s1.y = k5 + b_qkv[256 + (coff+5)*8 + head];
            s1.z = k6 + b_qkv[256 + (coff+6)*8 + head];
            s1.w = k7 + b_qkv[256 + (coff+7)*8 + head];
            ((float4*)(Ks + kk * 36 + coff))[0] = s0;
            ((float4*)(Ks + kk * 36 + coff))[1] = s1;
            s0.x = v0 + b_qkv[512 + (coff+0)*8 + head];
            s0.y = v1 + b_qkv[512 + (coff+1)*8 + head];
            s0.z = v2 + b_qkv[512 + (coff+2)*8 + head];
            s0.w = v3 + b_qkv[512 + (coff+3)*8 + head];
            s1.x = v4 + b_qkv[512 + (coff+4)*8 + head];
            s1.y = v5 + b_qkv[512 + (coff+5)*8 + head];
            s1.z = v6 + b_qkv[512 + (coff+6)*8 + head];
            s1.w = v7 + b_qkv[512 + (coff+7)*8 + head];
            ((float4*)(Vs + kk * 36 + coff))[0] = s0;
            ((float4*)(Vs + kk * 36 + coff))[1] = s1;
        }
        __syncthreads();

        // -- consume 128 keys --
        for (int j = 0; j < 128; j++) {
            const float4* kr = (const float4*)(Ks + j * 36 + qoff);
            float4 kA = kr[0], kB = kr[1], kC = kr[2], kD = kr[3];
            float sp = 0.f;
            sp = fmaf(q0,  kA.x, sp); sp = fmaf(q1,  kA.y, sp);
            sp = fmaf(q2,  kA.z, sp); sp = fmaf(q3,  kA.w, sp);
            sp = fmaf(q4,  kB.x, sp); sp = fmaf(q5,  kB.y, sp);
            sp = fmaf(q6,  kB.z, sp); sp = fmaf(q7,  kB.w, sp);
            sp = fmaf(q8,  kC.x, sp); sp = fmaf(q9,  kC.y, sp);
            sp = fmaf(q10, kC.z, sp); sp = fmaf(q11, kC.w, sp);
            sp = fmaf(q12, kD.x, sp); sp = fmaf(q13, kD.y, sp);
            sp = fmaf(q14, kD.z, sp); sp = fmaf(q15, kD.w, sp);
            float s = sp + __shfl_xor_sync(0xFFFFFFFFu, sp, 1);
            if (s > mx) {                          // rare rescale
                float corr = fast_exp(mx - s);
                l *= corr;
                a0*=corr; a1*=corr; a2*=corr; a3*=corr;
                a4*=corr; a5*=corr; a6*=corr; a7*=corr;
                a8*=corr; a9*=corr; a10*=corr; a11*=corr;
                a12*=corr; a13*=corr; a14*=corr; a15*=corr;
                mx = s;
            }
            float p = fast_exp(s - mx);
            l += p;
            const float4* vr = (const float4*)(Vs + j * 36 + qoff);
            float4 vA = vr[0], vB = vr[1], vC = vr[2], vD = vr[3];
            a0  = fmaf(p, vA.x, a0);  a1  = fmaf(p, vA.y, a1);
            a2  = fmaf(p, vA.z, a2);  a3  = fmaf(p, vA.w, a3);
            a4  = fmaf(p, vB.x, a4);  a5  = fmaf(p, vB.y, a5);
            a6  = fmaf(p, vB.z, a6);  a7  = fmaf(p, vB.w, a7);
            a8  = fmaf(p, vC.x, a8);  a9  = fmaf(p, vC.y, a9);
            a10 = fmaf(p, vC.z, a10); a11 = fmaf(p, vC.w, a11);
            a12 = fmaf(p, vD.x, a12); a13 = fmaf(p, vD.y, a13);
            a14 = fmaf(p, vD.z, a14); a15 = fmaf(p, vD.w, a15);
        }
        __syncthreads();    // Ks/Vs reads done before next tile's writes
    }

    // normalize o
    {
        float inv = 1.f / l;
        a0*=inv; a1*=inv; a2*=inv; a3*=inv; a4*=inv; a5*=inv; a6*=inv; a7*=inv;
        a8*=inv; a9*=inv; a10*=inv; a11*=inv; a12*=inv; a13*=inv; a14*=inv; a15*=inv;
    }

    // ---- Epilogue: fused output projection, atomicAdd into out ----
    __syncthreads();
#pragma unroll
    for (int r = 0; r < 16; r++) {
        int idx = tid + r * 512;          // 0..8191
        int oc = idx >> 5, cc = idx & 31;
        sm[oc * 32 + cc] = w_out[(size_t)oc * CC + cc * 8 + head];
    }
    __syncthreads();

    float* ob = out + (size_t)n * (CC * HW) + query;
    for (int oc = 0; oc < 256; oc++) {
        const float4* wr = (const float4*)(sm + oc * 32 + qoff);
        float4 wA = wr[0], wB = wr[1], wC = wr[2], wD = wr[3];
        float sp = 0.f;
        sp = fmaf(a0,  wA.x, sp); sp = fmaf(a1,  wA.y, sp);
        sp = fmaf(a2,  wA.z, sp); sp = fmaf(a3,  wA.w, sp);
        sp = fmaf(a4,  wB.x, sp); sp = fmaf(a5,  wB.y, sp);
        sp = fmaf(a6,  wB.z, sp); sp = fmaf(a7,  wB.w, sp);
        sp = fmaf(a8,  wC.x, sp); sp = fmaf(a9,  wC.y, sp);
        sp = fmaf(a10, wC.z, sp); sp = fmaf(a11, wC.w, sp);
        sp = fmaf(a12, wD.x, sp); sp = fmaf(a13, wD.y, sp);
        sp = fmaf(a14, wD.z, sp); sp = fmaf(a15, wD.w, sp);
        sp += __shfl_xor_sync(0xFFFFFFFFu, sp, 1);
        if (half == 0)
            atomicAdd(ob + (size_t)oc * HW, sp);
    }
}

// ---------------------------------------------------------------------------
extern "C" void kernel_launch(void* const* d_in, const int* in_sizes, int n_in,
                              void* d_out, int out_size)
{
    const float* x      = (const float*)d_in[0];
    const float* w_qkv  = (const float*)d_in[1];
    const float* b_qkv  = (const float*)d_in[2];
    const float* w_out  = (const float*)d_in[3];
    const float* b_out  = (const float*)d_in[4];
    const int*   access = (const int*)d_in[5];
    float* out = (float*)d_out;

    const int total = NT * CC * HW;                    // 3,407,872
    init_out<<<(total + 255) / 256, 256>>>(b_out, out, total);
    attn_fused<<<NT * NHEAD, 512>>>(x, w_qkv, b_qkv, w_out, access, out);
}

// round 12
// speedup vs baseline: 1.9754x; 1.9754x over previous
#include <cuda_runtime.h>
#include <cuda_fp16.h>
#include <math.h>

// Problem constants
#define TT 26
#define NB 2
#define NT (NB*TT)      // 52 frames
#define CC 256
#define HW 256          // 16*16
#define NHEAD 8
#define CPH 32          // C / NHEAD

// fp16 K/V cache, head-major: [((n*8+head)*256 + hw)*32 + cph]
__device__ __half g_k[(size_t)NT * NHEAD * HW * CPH];   // 6.8 MB
__device__ __half g_v[(size_t)NT * NHEAD * HW * CPH];   // 6.8 MB

// Register-only fp16 unpack helpers (no address-of-local anywhere).
__device__ __forceinline__ float h2f_lo(unsigned u) {
    return __half2float(__ushort_as_half((unsigned short)(u & 0xFFFFu)));
}
__device__ __forceinline__ float h2f_hi(unsigned u) {
    return __half2float(__ushort_as_half((unsigned short)(u >> 16)));
}

// Fast exp on the FMA pipe (input <= 0).
__device__ __forceinline__ float fast_exp(float x) {
    float y = fmaxf(x, -87.0f) * 1.4426950408889634f;
    float fn = y + 12582912.0f;                 // 1.5 * 2^23 magic round
    int n = __float_as_int(fn) - 0x4B400000;
    float r = y - (fn - 12582912.0f);
    float p = 1.3333558146e-3f;
    p = fmaf(p, r, 9.6181291794e-3f);
    p = fmaf(p, r, 5.5504108664e-2f);
    p = fmaf(p, r, 2.4022650696e-1f);
    p = fmaf(p, r, 6.9314718056e-1f);
    p = fmaf(p, r, 1.0f);
    return p * __int_as_float((n + 127) << 23);
}

// ---------------------------------------------------------------------------
// init_out: out[n][oc][hw] = b_out[oc]
// ---------------------------------------------------------------------------
__global__ __launch_bounds__(256, 1)
void init_out(const float* __restrict__ b_out, float* __restrict__ out, int total)
{
    int i = blockIdx.x * blockDim.x + threadIdx.x;
    if (i < total) out[i] = b_out[(i >> 8) & 255];
}

// ---------------------------------------------------------------------------
// kv_proj: K/V projection GEMM. val(m, o) = sum_c x[n][c][hw]*w_qkv[256+o][c]
// + b_qkv[256+o], o in [0,512): [0,256)=k, [256,512)=v. fp16 scatter into
// g_k/g_v head-major. 256 threads, 64x64x16 tile, 4x4/thread, named scalars.
// ---------------------------------------------------------------------------
__global__ __launch_bounds__(256, 1)
void kv_proj(const float* __restrict__ x,
             const float* __restrict__ w_qkv,
             const float* __restrict__ b_qkv)
{
    __shared__ __align__(16) float As[16][64];
    __shared__ __align__(16) float Bs[16][72];

    const int tid = threadIdx.x;
    const int tx = tid & 15;
    const int ty = tid >> 4;

    const int m0  = blockIdx.x * 64;
    const int nn  = m0 >> 8;
    const int hwb = m0 & 255;
    const int o0  = blockIdx.y * 64;

    const float* Ab = x + (size_t)nn * CC * HW + hwb;

    const int am = tid & 63;
    const int ac = tid >> 6;
    const int boo = tid >> 2;
    const int bc4 = (tid & 3) * 4;

    float c00=0.f,c01=0.f,c02=0.f,c03=0.f;
    float c10=0.f,c11=0.f,c12=0.f,c13=0.f;
    float c20=0.f,c21=0.f,c22=0.f,c23=0.f;
    float c30=0.f,c31=0.f,c32=0.f,c33=0.f;

    for (int k0 = 0; k0 < CC; k0 += 16) {
        As[ac +  0][am] = Ab[(size_t)(k0 + ac +  0) * HW + am];
        As[ac +  4][am] = Ab[(size_t)(k0 + ac +  4) * HW + am];
        As[ac +  8][am] = Ab[(size_t)(k0 + ac +  8) * HW + am];
        As[ac + 12][am] = Ab[(size_t)(k0 + ac + 12) * HW + am];
        {
            float4 wv = *(const float4*)&w_qkv[(size_t)(256 + o0 + boo) * CC + k0 + bc4];
            Bs[bc4 + 0][boo] = wv.x;
            Bs[bc4 + 1][boo] = wv.y;
            Bs[bc4 + 2][boo] = wv.z;
            Bs[bc4 + 3][boo] = wv.w;
        }
        __syncthreads();

#pragma unroll
        for (int k = 0; k < 16; k++) {
            float4 a4 = *(const float4*)&As[k][tx * 4];
            float4 b4 = *(const float4*)&Bs[k][ty * 4];
            c00 = fmaf(a4.x, b4.x, c00); c01 = fmaf(a4.x, b4.y, c01);
            c02 = fmaf(a4.x, b4.z, c02); c03 = fmaf(a4.x, b4.w, c03);
            c10 = fmaf(a4.y, b4.x, c10); c11 = fmaf(a4.y, b4.y, c11);
            c12 = fmaf(a4.y, b4.z, c12); c13 = fmaf(a4.y, b4.w, c13);
            c20 = fmaf(a4.z, b4.x, c20); c21 = fmaf(a4.z, b4.y, c21);
            c22 = fmaf(a4.z, b4.z, c22); c23 = fmaf(a4.z, b4.w, c23);
            c30 = fmaf(a4.w, b4.x, c30); c31 = fmaf(a4.w, b4.y, c31);
            c32 = fmaf(a4.w, b4.z, c32); c33 = fmaf(a4.w, b4.w, c33);
        }
        __syncthreads();
    }

    // Epilogue: scatter fp16 into g_k / g_v.
#define KV_EPI(J, A0, A1, A2, A3)                                              \
    {                                                                          \
        int o = o0 + ty * 4 + (J);                                             \
        float bb = b_qkv[256 + o];                                             \
        int c = o & 255;                                                       \
        int head = c & 7;                                                      \
        int cph  = c >> 3;                                                     \
        __half* dst = (o < 256) ? g_k : g_v;                                   \
        __half* dp = dst + (((size_t)nn * 8 + head) * 256 + hwb + tx * 4) * 32 + cph; \
        dp[0]  = __float2half((A0) + bb);                                      \
        dp[32] = __float2half((A1) + bb);                                      \
        dp[64] = __float2half((A2) + bb);                                      \
        dp[96] = __float2half((A3) + bb);                                      \
    }
    KV_EPI(0, c00, c10, c20, c30)
    KV_EPI(1, c01, c11, c21, c31)
    KV_EPI(2, c02, c12, c22, c32)
    KV_EPI(3, c03, c13, c23, c33)
#undef KV_EPI
}

// ---------------------------------------------------------------------------
// Fused attention + output projection. One block per (frame n, head).
// 512 threads = 2 threads per query (each owns 16 of 32 channels).
// K/V tiles loaded from the fp16 cache (no recompute).
// ---------------------------------------------------------------------------
__global__ __launch_bounds__(512, 1)
void attn_fused(const float* __restrict__ x,
                const float* __restrict__ w_qkv,
                const float* __restrict__ b_qkv,
                const float* __restrict__ w_out,
                const int* __restrict__ access,
                float* __restrict__ out)
{
    // Ks[128][36] @0 (4608), Vs[128][36] @4608, Wq[32][32] @9216.
    // Epilogue overlays woT[256][32] @0.
    __shared__ __align__(16) float sm[10240];
    float* Ks = sm;
    float* Vs = sm + 4608;
    float* Wq = sm + 9216;

    const int tid   = threadIdx.x;
    const int query = tid >> 1;
    const int half  = tid & 1;
    const int qoff  = half * 16;
    const int bid   = blockIdx.x;
    const int n     = bid >> 3;
    const int head  = bid & 7;
    const int t     = n % TT;
    const int b_    = n / TT;

    // ---- Phase A: recompute q[16] from x, chunked Wq staging ----
    float q0=0.f,q1=0.f,q2=0.f,q3=0.f,q4=0.f,q5=0.f,q6=0.f,q7=0.f;
    float q8=0.f,q9=0.f,q10=0.f,q11=0.f,q12=0.f,q13=0.f,q14=0.f,q15=0.f;

    const float* xq = x + (size_t)n * (CC * HW) + query;
    for (int c0 = 0; c0 < 256; c0 += 32) {
        __syncthreads();
        {
            int idx = tid;
            int ch = idx & 31, cc = idx >> 5;
            Wq[ch * 32 + cc] = w_qkv[(size_t)(cc * 8 + head) * CC + c0 + ch];
            idx = tid + 512;
            ch = idx & 31; cc = idx >> 5;
            Wq[ch * 32 + cc] = w_qkv[(size_t)(cc * 8 + head) * CC + c0 + ch];
        }
        __syncthreads();
#pragma unroll 8
        for (int ch = 0; ch < 32; ch++) {
            float xv = xq[(size_t)(c0 + ch) * HW];
            const float4* wr = (const float4*)(Wq + ch * 32 + qoff);
            float4 w0 = wr[0], w1 = wr[1], w2 = wr[2], w3 = wr[3];
            q0  = fmaf(xv, w0.x, q0);  q1  = fmaf(xv, w0.y, q1);
            q2  = fmaf(xv, w0.z, q2);  q3  = fmaf(xv, w0.w, q3);
            q4  = fmaf(xv, w1.x, q4);  q5  = fmaf(xv, w1.y, q5);
            q6  = fmaf(xv, w1.z, q6);  q7  = fmaf(xv, w1.w, q7);
            q8  = fmaf(xv, w2.x, q8);  q9  = fmaf(xv, w2.y, q9);
            q10 = fmaf(xv, w2.z, q10); q11 = fmaf(xv, w2.w, q11);
            q12 = fmaf(xv, w3.x, q12); q13 = fmaf(xv, w3.y, q13);
            q14 = fmaf(xv, w3.z, q14); q15 = fmaf(xv, w3.w, q15);
        }
    }
    const float scale = 0.17677669529663687f;   // 1/sqrt(32)
    q0  = (q0  + b_qkv[(qoff+0)*8+head])  * scale;
    q1  = (q1  + b_qkv[(qoff+1)*8+head])  * scale;
    q2  = (q2  + b_qkv[(qoff+2)*8+head])  * scale;
    q3  = (q3  + b_qkv[(qoff+3)*8+head])  * scale;
    q4  = (q4  + b_qkv[(qoff+4)*8+head])  * scale;
    q5  = (q5  + b_qkv[(qoff+5)*8+head])  * scale;
    q6  = (q6  + b_qkv[(qoff+6)*8+head])  * scale;
    q7  = (q7  + b_qkv[(qoff+7)*8+head])  * scale;
    q8  = (q8  + b_qkv[(qoff+8)*8+head])  * scale;
    q9  = (q9  + b_qkv[(qoff+9)*8+head])  * scale;
    q10 = (q10 + b_qkv[(qoff+10)*8+head]) * scale;
    q11 = (q11 + b_qkv[(qoff+11)*8+head]) * scale;
    q12 = (q12 + b_qkv[(qoff+12)*8+head]) * scale;
    q13 = (q13 + b_qkv[(qoff+13)*8+head]) * scale;
    q14 = (q14 + b_qkv[(qoff+14)*8+head]) * scale;
    q15 = (q15 + b_qkv[(qoff+15)*8+head]) * scale;

    // ---- Online softmax over 4 gathered frames x 2 half-tiles of 128 keys ----
    float mx = -1e30f, l = 0.f;
    float a0=0.f,a1=0.f,a2=0.f,a3=0.f,a4=0.f,a5=0.f,a6=0.f,a7=0.f;
    float a8=0.f,a9=0.f,a10=0.f,a11=0.f,a12=0.f,a13=0.f,a14=0.f,a15=0.f;

    const int kk   = tid >> 2;            // key 0..127 (load mapping)
    const int coff = (tid & 3) * 8;       // channel group 0,8,16,24

    for (int tt = 0; tt < 8; tt++) {
        const int g  = tt >> 1;
        const int hf = tt & 1;
        const int f  = access[t * 4 + g];
        const int nf = b_ * TT + f;
        const size_t kvbase = (((size_t)nf * 8 + head) * 256 + hf * 128 + kk) * 32 + coff;

        // -- load K/V tile from fp16 cache: 1 uint4 each per thread --
        {
            uint4 rk = *(const uint4*)(g_k + kvbase);
            float4 s0, s1;
            s0.x = h2f_lo(rk.x); s0.y = h2f_hi(rk.x);
            s0.z = h2f_lo(rk.y); s0.w = h2f_hi(rk.y);
            s1.x = h2f_lo(rk.z); s1.y = h2f_hi(rk.z);
            s1.z = h2f_lo(rk.w); s1.w = h2f_hi(rk.w);
            ((float4*)(Ks + kk * 36 + coff))[0] = s0;
            ((float4*)(Ks + kk * 36 + coff))[1] = s1;
            uint4 rv = *(const uint4*)(g_v + kvbase);
            s0.x = h2f_lo(rv.x); s0.y = h2f_hi(rv.x);
            s0.z = h2f_lo(rv.y); s0.w = h2f_hi(rv.y);
            s1.x = h2f_lo(rv.z); s1.y = h2f_hi(rv.z);
            s1.z = h2f_lo(rv.w); s1.w = h2f_hi(rv.w);
            ((float4*)(Vs + kk * 36 + coff))[0] = s0;
            ((float4*)(Vs + kk * 36 + coff))[1] = s1;
        }
        __syncthreads();

        // -- consume 128 keys --
        for (int j = 0; j < 128; j++) {
            const float4* kr = (const float4*)(Ks + j * 36 + qoff);
            float4 kA = kr[0], kB = kr[1], kC = kr[2], kD = kr[3];
            float sp0 = 0.f, sp1 = 0.f, sp2 = 0.f, sp3 = 0.f;
            sp0 = fmaf(q0,  kA.x, sp0); sp0 = fmaf(q1,  kA.y, sp0);
            sp0 = fmaf(q2,  kA.z, sp0); sp0 = fmaf(q3,  kA.w, sp0);
            sp1 = fmaf(q4,  kB.x, sp1); sp1 = fmaf(q5,  kB.y, sp1);
            sp1 = fmaf(q6,  kB.z, sp1); sp1 = fmaf(q7,  kB.w, sp1);
            sp2 = fmaf(q8,  kC.x, sp2); sp2 = fmaf(q9,  kC.y, sp2);
            sp2 = fmaf(q10, kC.z, sp2); sp2 = fmaf(q11, kC.w, sp2);
            sp3 = fmaf(q12, kD.x, sp3); sp3 = fmaf(q13, kD.y, sp3);
            sp3 = fmaf(q14, kD.z, sp3); sp3 = fmaf(q15, kD.w, sp3);
            float sp = (sp0 + sp1) + (sp2 + sp3);
            float s = sp + __shfl_xor_sync(0xFFFFFFFFu, sp, 1);
            if (s > mx) {                          // rare rescale
                float corr = fast_exp(mx - s);
                l *= corr;
                a0*=corr; a1*=corr; a2*=corr; a3*=corr;
                a4*=corr; a5*=corr; a6*=corr; a7*=corr;
                a8*=corr; a9*=corr; a10*=corr; a11*=corr;
                a12*=corr; a13*=corr; a14*=corr; a15*=corr;
                mx = s;
            }
            float p = fast_exp(s - mx);
            l += p;
            const float4* vr = (const float4*)(Vs + j * 36 + qoff);
            float4 vA = vr[0], vB = vr[1], vC = vr[2], vD = vr[3];
            a0  = fmaf(p, vA.x, a0);  a1  = fmaf(p, vA.y, a1);
            a2  = fmaf(p, vA.z, a2);  a3  = fmaf(p, vA.w, a3);
            a4  = fmaf(p, vB.x, a4);  a5  = fmaf(p, vB.y, a5);
            a6  = fmaf(p, vB.z, a6);  a7  = fmaf(p, vB.w, a7);
            a8  = fmaf(p, vC.x, a8);  a9  = fmaf(p, vC.y, a9);
            a10 = fmaf(p, vC.z, a10); a11 = fmaf(p, vC.w, a11);
            a12 = fmaf(p, vD.x, a12); a13 = fmaf(p, vD.y, a13);
            a14 = fmaf(p, vD.z, a14); a15 = fmaf(p, vD.w, a15);
        }
        __syncthreads();    // Ks/Vs reads done before next tile's writes
    }

    // normalize
    {
        float inv = 1.f / l;
        a0*=inv; a1*=inv; a2*=inv; a3*=inv; a4*=inv; a5*=inv; a6*=inv; a7*=inv;
        a8*=inv; a9*=inv; a10*=inv; a11*=inv; a12*=inv; a13*=inv; a14*=inv; a15*=inv;
    }

    // ---- Epilogue: fused output projection, atomicAdd into out ----
    __syncthreads();
#pragma unroll
    for (int r = 0; r < 16; r++) {
        int idx = tid + r * 512;
        int oc = idx >> 5, cc = idx & 31;
        sm[oc * 32 + cc] = w_out[(size_t)oc * CC + cc * 8 + head];
    }
    __syncthreads();

    float* ob = out + (size_t)n * (CC * HW) + query;
    for (int oc = 0; oc < 256; oc++) {
        const float4* wr = (const float4*)(sm + oc * 32 + qoff);
        float4 wA = wr[0], wB = wr[1], wC = wr[2], wD = wr[3];
        float sp0 = 0.f, sp1 = 0.f;
        sp0 = fmaf(a0,  wA.x, sp0); sp0 = fmaf(a1,  wA.y, sp0);
        sp0 = fmaf(a2,  wA.z, sp0); sp0 = fmaf(a3,  wA.w, sp0);
        sp0 = fmaf(a4,  wB.x, sp0); sp0 = fmaf(a5,  wB.y, sp0);
        sp0 = fmaf(a6,  wB.z, sp0); sp0 = fmaf(a7,  wB.w, sp0);
        sp1 = fmaf(a8,  wC.x, sp1); sp1 = fmaf(a9,  wC.y, sp1);
        sp1 = fmaf(a10, wC.z, sp1); sp1 = fmaf(a11, wC.w, sp1);
        sp1 = fmaf(a12, wD.x, sp1); sp1 = fmaf(a13, wD.y, sp1);
        sp1 = fmaf(a14, wD.z, sp1); sp1 = fmaf(a15, wD.w, sp1);
        float sp = sp0 + sp1;
        sp += __shfl_xor_sync(0xFFFFFFFFu, sp, 1);
        if (half == 0)
            atomicAdd(ob + (size_t)oc * HW, sp);
    }
}

// ---------------------------------------------------------------------------
extern "C" void kernel_launch(void* const* d_in, const int* in_sizes, int n_in,
                              void* d_out, int out_size)
{
    const float* x      = (const float*)d_in[0];
    const float* w_qkv  = (const float*)d_in[1];
    const float* b_qkv  = (const float*)d_in[2];
    const float* w_out  = (const float*)d_in[3];
    const float* b_out  = (const float*)d_in[4];
    const int*   access = (const int*)d_in[5];
    float* out = (float*)d_out;

    const int total = NT * CC * HW;
    init_out<<<(total + 255) / 256, 256>>>(b_out, out, total);
    {
        dim3 grid(NT * HW / 64, 512 / 64);    // 208 x 8
        kv_proj<<<grid, 256>>>(x, w_qkv, b_qkv);
    }
    attn_fused<<<NT * NHEAD, 512>>>(x, w_qkv, b_qkv, w_out, access, out);
}

// round 13
// speedup vs baseline: 4.3299x; 2.1919x over previous
#include <cuda_runtime.h>
#include <cuda_fp16.h>
#include <math.h>

// Problem constants
#define TT 26
#define NB 2
#define NT (NB*TT)      // 52 frames
#define CC 256
#define HW 256          // 16*16
#define NHEAD 8
#define CPH 32          // C / NHEAD

// fp16 K/V cache, head-major: [((n*8+head)*256 + hw)*32 + cph]
__device__ __half g_k[(size_t)NT * NHEAD * HW * CPH];   // 6.8 MB
__device__ __half g_v[(size_t)NT * NHEAD * HW * CPH];   // 6.8 MB
// fp16 attention output, projection layout: [n][c=cph*8+head][hw]
__device__ __half g_o[(size_t)NT * CC * HW];            // 6.8 MB

// Fast 2^x on the FMA pipe (x <= 0). r in [-0.5,0.5] poly.
__device__ __forceinline__ float fast_exp2(float x) {
    float y = fmaxf(x, -126.0f);
    float fn = y + 12582912.0f;                 // 1.5 * 2^23 magic round
    int n = __float_as_int(fn) - 0x4B400000;
    float r = y - (fn - 12582912.0f);
    float p = 1.3333558146e-3f;
    p = fmaf(p, r, 9.6181291794e-3f);
    p = fmaf(p, r, 5.5504108664e-2f);
    p = fmaf(p, r, 2.4022650696e-1f);
    p = fmaf(p, r, 6.9314718056e-1f);
    p = fmaf(p, r, 1.0f);
    return p * __int_as_float((n + 127) << 23);
}

// ---- PTX wrappers -------------------------------------------------------
#define LDSMX2(R0, R1, ADDR) \
    asm volatile("ldmatrix.sync.aligned.m8n8.x2.shared.b16 {%0,%1},[%2];" \
                 : "=r"(R0), "=r"(R1) : "r"(ADDR))
#define LDSMX2T(R0, R1, ADDR) \
    asm volatile("ldmatrix.sync.aligned.m8n8.x2.trans.shared.b16 {%0,%1},[%2];" \
                 : "=r"(R0), "=r"(R1) : "r"(ADDR))
#define LDSMX4(R0, R1, R2, R3, ADDR) \
    asm volatile("ldmatrix.sync.aligned.m8n8.x4.shared.b16 {%0,%1,%2,%3},[%4];" \
                 : "=r"(R0), "=r"(R1), "=r"(R2), "=r"(R3) : "r"(ADDR))
#define MMA(C0, C1, C2, C3, A0, A1, A2, A3, B0, B1) \
    asm volatile("mma.sync.aligned.m16n8k16.row.col.f32.f16.f16.f32 " \
                 "{%0,%1,%2,%3},{%4,%5,%6,%7},{%8,%9},{%0,%1,%2,%3};" \
                 : "+f"(C0), "+f"(C1), "+f"(C2), "+f"(C3) \
                 : "r"(A0), "r"(A1), "r"(A2), "r"(A3), "r"(B0), "r"(B1))
// U = {lo=LO, hi=HI} as f16x2
#define H2(U, LO, HI) \
    asm("cvt.rn.f16x2.f32 %0,%1,%2;" : "=r"(U) : "f"(HI), "f"(LO))

// ---------------------------------------------------------------------------
// kv_proj: K/V projection GEMM (unchanged from R12, proven).
// ---------------------------------------------------------------------------
__global__ __launch_bounds__(256, 1)
void kv_proj(const float* __restrict__ x,
             const float* __restrict__ w_qkv,
             const float* __restrict__ b_qkv)
{
    __shared__ __align__(16) float As[16][64];
    __shared__ __align__(16) float Bs[16][72];

    const int tid = threadIdx.x;
    const int tx = tid & 15;
    const int ty = tid >> 4;

    const int m0  = blockIdx.x * 64;
    const int nn  = m0 >> 8;
    const int hwb = m0 & 255;
    const int o0  = blockIdx.y * 64;

    const float* Ab = x + (size_t)nn * CC * HW + hwb;

    const int am = tid & 63;
    const int ac = tid >> 6;
    const int boo = tid >> 2;
    const int bc4 = (tid & 3) * 4;

    float c00=0.f,c01=0.f,c02=0.f,c03=0.f;
    float c10=0.f,c11=0.f,c12=0.f,c13=0.f;
    float c20=0.f,c21=0.f,c22=0.f,c23=0.f;
    float c30=0.f,c31=0.f,c32=0.f,c33=0.f;

    for (int k0 = 0; k0 < CC; k0 += 16) {
        As[ac +  0][am] = Ab[(size_t)(k0 + ac +  0) * HW + am];
        As[ac +  4][am] = Ab[(size_t)(k0 + ac +  4) * HW + am];
        As[ac +  8][am] = Ab[(size_t)(k0 + ac +  8) * HW + am];
        As[ac + 12][am] = Ab[(size_t)(k0 + ac + 12) * HW + am];
        {
            float4 wv = *(const float4*)&w_qkv[(size_t)(256 + o0 + boo) * CC + k0 + bc4];
            Bs[bc4 + 0][boo] = wv.x;
            Bs[bc4 + 1][boo] = wv.y;
            Bs[bc4 + 2][boo] = wv.z;
            Bs[bc4 + 3][boo] = wv.w;
        }
        __syncthreads();
#pragma unroll
        for (int k = 0; k < 16; k++) {
            float4 a4 = *(const float4*)&As[k][tx * 4];
            float4 b4 = *(const float4*)&Bs[k][ty * 4];
            c00 = fmaf(a4.x, b4.x, c00); c01 = fmaf(a4.x, b4.y, c01);
            c02 = fmaf(a4.x, b4.z, c02); c03 = fmaf(a4.x, b4.w, c03);
            c10 = fmaf(a4.y, b4.x, c10); c11 = fmaf(a4.y, b4.y, c11);
            c12 = fmaf(a4.y, b4.z, c12); c13 = fmaf(a4.y, b4.w, c13);
            c20 = fmaf(a4.z, b4.x, c20); c21 = fmaf(a4.z, b4.y, c21);
            c22 = fmaf(a4.z, b4.z, c22); c23 = fmaf(a4.z, b4.w, c23);
            c30 = fmaf(a4.w, b4.x, c30); c31 = fmaf(a4.w, b4.y, c31);
            c32 = fmaf(a4.w, b4.z, c32); c33 = fmaf(a4.w, b4.w, c33);
        }
        __syncthreads();
    }

#define KV_EPI(J, A0, A1, A2, A3)                                              \
    {                                                                          \
        int o = o0 + ty * 4 + (J);                                             \
        float bb = b_qkv[256 + o];                                             \
        int c = o & 255;                                                       \
        int head = c & 7;                                                      \
        int cph  = c >> 3;                                                     \
        __half* dst = (o < 256) ? g_k : g_v;                                   \
        __half* dp = dst + (((size_t)nn * 8 + head) * 256 + hwb + tx * 4) * 32 + cph; \
        dp[0]  = __float2half((A0) + bb);                                      \
        dp[32] = __float2half((A1) + bb);                                      \
        dp[64] = __float2half((A2) + bb);                                      \
        dp[96] = __float2half((A3) + bb);                                      \
    }
    KV_EPI(0, c00, c10, c20, c30)
    KV_EPI(1, c01, c11, c21, c31)
    KV_EPI(2, c02, c12, c22, c32)
    KV_EPI(3, c03, c13, c23, c33)
#undef KV_EPI
}

// ---------------------------------------------------------------------------
// Tensor-core flash attention. One block per (frame n, head); 256 threads.
// Warp w owns queries [w*32, w*32+32). fp16 mma m16n8k16, fp32 accum,
// exp2-domain online softmax (scale*log2e folded into Q).
// ---------------------------------------------------------------------------
__global__ __launch_bounds__(256, 1)
void attn_tc(const float* __restrict__ x,
             const float* __restrict__ w_qkv,
             const float* __restrict__ b_qkv,
             const int* __restrict__ access)
{
    // Halves: Qs[256][40] @0, Ks[128][40] @10240, Vs[128][40] @15360
    __shared__ __align__(16) __half sm_h[20480];

    const int tid  = threadIdx.x;
    const int w    = tid >> 5;
    const int l    = tid & 31;
    const int bid  = blockIdx.x;
    const int n    = bid >> 3;
    const int head = bid & 7;
    const int t    = n % TT;
    const int b_   = n / TT;

    unsigned sbase;
    asm("{ .reg .u64 t0; cvta.to.shared.u64 t0, %1; cvt.u32.u64 %0, t0; }"
        : "=r"(sbase) : "l"(sm_h));
    const unsigned qs_u = sbase;
    const unsigned ks_u = sbase + 20480;
    const unsigned vs_u = sbase + 30720;

    // ---- Phase A: Q = x @ WqT + b, scaled by (1/sqrt(32))*log2(e), fp16 ----
    float* Wst = (float*)(sm_h + 10240);    // 256x16 fp32 = 16 KB over Ks/Vs
    const float qscale = 0.17677669529663687f * 1.4426950408889634f;
#pragma unroll
    for (int s = 0; s < 2; s++) {
        __syncthreads();
#pragma unroll
        for (int r = 0; r < 16; r++)
            Wst[tid * 16 + r] = w_qkv[(size_t)((s * 16 + r) * 8 + head) * CC + tid];
        __syncthreads();
        float q0=0.f,q1=0.f,q2=0.f,q3=0.f,q4=0.f,q5=0.f,q6=0.f,q7=0.f;
        float q8=0.f,q9=0.f,q10=0.f,q11=0.f,q12=0.f,q13=0.f,q14=0.f,q15=0.f;
        const float* xp = x + (size_t)n * (CC * HW) + tid;
#pragma unroll 4
        for (int c = 0; c < 256; c++) {
            float xv = xp[(size_t)c * HW];
            const float4* wr = (const float4*)(Wst + c * 16);
            float4 w0 = wr[0], w1 = wr[1], w2 = wr[2], w3 = wr[3];
            q0  = fmaf(xv, w0.x, q0);  q1  = fmaf(xv, w0.y, q1);
            q2  = fmaf(xv, w0.z, q2);  q3  = fmaf(xv, w0.w, q3);
            q4  = fmaf(xv, w1.x, q4);  q5  = fmaf(xv, w1.y, q5);
            q6  = fmaf(xv, w1.z, q6);  q7  = fmaf(xv, w1.w, q7);
            q8  = fmaf(xv, w2.x, q8);  q9  = fmaf(xv, w2.y, q9);
            q10 = fmaf(xv, w2.z, q10); q11 = fmaf(xv, w2.w, q11);
            q12 = fmaf(xv, w3.x, q12); q13 = fmaf(xv, w3.y, q13);
            q14 = fmaf(xv, w3.z, q14); q15 = fmaf(xv, w3.w, q15);
        }
#define QFIN(QA, QB, K)                                                        \
        {                                                                      \
            float fa = (QA + b_qkv[(s*16 + 2*(K)    )*8 + head]) * qscale;     \
            float fb = (QB + b_qkv[(s*16 + 2*(K) + 1)*8 + head]) * qscale;     \
            unsigned u; H2(u, fa, fb);                                         \
            *(unsigned*)((char*)sm_h + tid * 80 + s * 32 + (K) * 4) = u;       \
        }
        QFIN(q0,q1,0) QFIN(q2,q3,1) QFIN(q4,q5,2) QFIN(q6,q7,3)
        QFIN(q8,q9,4) QFIN(q10,q11,5) QFIN(q12,q13,6) QFIN(q14,q15,7)
#undef QFIN
    }
    __syncthreads();

    // ---- Load Q a-frags (persist in registers) ----
    unsigned aqA0_0,aqA0_1,aqA0_2,aqA0_3, aqA1_0,aqA1_1,aqA1_2,aqA1_3;
    unsigned aqB0_0,aqB0_1,aqB0_2,aqB0_3, aqB1_0,aqB1_1,aqB1_2,aqB1_3;
    {
        unsigned qrow = qs_u + (w * 32 + (l & 15)) * 80 + (l >> 4) * 16;
        LDSMX4(aqA0_0,aqA0_1,aqA0_2,aqA0_3, qrow);
        LDSMX4(aqA1_0,aqA1_1,aqA1_2,aqA1_3, qrow + 32);
        LDSMX4(aqB0_0,aqB0_1,aqB0_2,aqB0_3, qrow + 16*80);
        LDSMX4(aqB1_0,aqB1_1,aqB1_2,aqB1_3, qrow + 16*80 + 32);
    }

    // per-lane ldmatrix bases
    const unsigned k_lane = ks_u + (l & 7) * 80 + ((l >> 3) & 1) * 16;
    const unsigned v_lane = vs_u + (l & 15) * 80;

    // softmax state (rows r0=l>>2, r1=r0+8 per mtile)
    float mA0 = -1e30f, mA1 = -1e30f, mB0 = -1e30f, mB1 = -1e30f;
    float lA0 = 0.f, lA1 = 0.f, lB0 = 0.f, lB1 = 0.f;
    float oA0_0=0.f,oA0_1=0.f,oA0_2=0.f,oA0_3=0.f, oA1_0=0.f,oA1_1=0.f,oA1_2=0.f,oA1_3=0.f;
    float oA2_0=0.f,oA2_1=0.f,oA2_2=0.f,oA2_3=0.f, oA3_0=0.f,oA3_1=0.f,oA3_2=0.f,oA3_3=0.f;
    float oB0_0=0.f,oB0_1=0.f,oB0_2=0.f,oB0_3=0.f, oB1_0=0.f,oB1_1=0.f,oB1_2=0.f,oB1_3=0.f;
    float oB2_0=0.f,oB2_1=0.f,oB2_2=0.f,oB2_3=0.f, oB3_0=0.f,oB3_1=0.f,oB3_2=0.f,oB3_3=0.f;

    for (int tt = 0; tt < 8; tt++) {
        const int f  = access[t * 4 + (tt >> 1)];
        const int nf = b_ * TT + f;
        const size_t kvbase = (((size_t)nf * 8 + head) * 256 + (tt & 1) * 128) * 32;

        __syncthreads();
        {
            // 128 rows x 32 halves per tensor; 2 uint4 per thread per tensor.
#pragma unroll
            for (int u = 0; u < 2; u++) {
                int lin = tid * 2 + u;
                int row = lin >> 2, cb16 = (lin & 3) * 16;
                uint4 rk = *((const uint4*)(g_k + kvbase) + lin);
                *(uint4*)((char*)sm_h + 20480 + row * 80 + cb16) = rk;
                uint4 rv = *((const uint4*)(g_v + kvbase) + lin);
                *(uint4*)((char*)sm_h + 30720 + row * 80 + cb16) = rv;
            }
        }
        __syncthreads();

#pragma unroll
        for (int cc = 0; cc < 4; cc++) {
            const int c32 = cc * 32;
            const unsigned kA = k_lane + c32 * 80;
            const unsigned vA = v_lane + c32 * 80;

            float sA0_0=0.f,sA0_1=0.f,sA0_2=0.f,sA0_3=0.f, sA1_0=0.f,sA1_1=0.f,sA1_2=0.f,sA1_3=0.f;
            float sA2_0=0.f,sA2_1=0.f,sA2_2=0.f,sA2_3=0.f, sA3_0=0.f,sA3_1=0.f,sA3_2=0.f,sA3_3=0.f;
            float sB0_0=0.f,sB0_1=0.f,sB0_2=0.f,sB0_3=0.f, sB1_0=0.f,sB1_1=0.f,sB1_2=0.f,sB1_3=0.f;
            float sB2_0=0.f,sB2_1=0.f,sB2_2=0.f,sB2_3=0.f, sB3_0=0.f,sB3_1=0.f,sB3_2=0.f,sB3_3=0.f;

#define QK_NT(J) do { unsigned b0,b1,b2,b3;                                    \
            LDSMX2(b0, b1, kA + (J)*640);                                      \
            LDSMX2(b2, b3, kA + (J)*640 + 32);                                 \
            MMA(sA##J##_0,sA##J##_1,sA##J##_2,sA##J##_3, aqA0_0,aqA0_1,aqA0_2,aqA0_3, b0,b1); \
            MMA(sA##J##_0,sA##J##_1,sA##J##_2,sA##J##_3, aqA1_0,aqA1_1,aqA1_2,aqA1_3, b2,b3); \
            MMA(sB##J##_0,sB##J##_1,sB##J##_2,sB##J##_3, aqB0_0,aqB0_1,aqB0_2,aqB0_3, b0,b1); \
            MMA(sB##J##_0,sB##J##_1,sB##J##_2,sB##J##_3, aqB1_0,aqB1_1,aqB1_2,aqB1_3, b2,b3); \
        } while (0)
            QK_NT(0); QK_NT(1); QK_NT(2); QK_NT(3);
#undef QK_NT

            // --- online softmax (branchless, exp2 domain) ---
            float h0, h1, cA0, cA1, cB0, cB1;
            h0 = fmaxf(fmaxf(fmaxf(sA0_0,sA0_1),fmaxf(sA1_0,sA1_1)),
                       fmaxf(fmaxf(sA2_0,sA2_1),fmaxf(sA3_0,sA3_1)));
            h1 = fmaxf(fmaxf(fmaxf(sA0_2,sA0_3),fmaxf(sA1_2,sA1_3)),
                       fmaxf(fmaxf(sA2_2,sA2_3),fmaxf(sA3_2,sA3_3)));
            h0 = fmaxf(h0, __shfl_xor_sync(0xFFFFFFFFu, h0, 1));
            h0 = fmaxf(h0, __shfl_xor_sync(0xFFFFFFFFu, h0, 2));
            h1 = fmaxf(h1, __shfl_xor_sync(0xFFFFFFFFu, h1, 1));
            h1 = fmaxf(h1, __shfl_xor_sync(0xFFFFFFFFu, h1, 2));
            {
                float mn0 = fmaxf(mA0, h0), mn1 = fmaxf(mA1, h1);
                cA0 = fast_exp2(mA0 - mn0); cA1 = fast_exp2(mA1 - mn1);
                mA0 = mn0; mA1 = mn1;
            }
            h0 = fmaxf(fmaxf(fmaxf(sB0_0,sB0_1),fmaxf(sB1_0,sB1_1)),
                       fmaxf(fmaxf(sB2_0,sB2_1),fmaxf(sB3_0,sB3_1)));
            h1 = fmaxf(fmaxf(fmaxf(sB0_2,sB0_3),fmaxf(sB1_2,sB1_3)),
                       fmaxf(fmaxf(sB2_2,sB2_3),fmaxf(sB3_2,sB3_3)));
            h0 = fmaxf(h0, __shfl_xor_sync(0xFFFFFFFFu, h0, 1));
            h0 = fmaxf(h0, __shfl_xor_sync(0xFFFFFFFFu, h0, 2));
            h1 = fmaxf(h1, __shfl_xor_sync(0xFFFFFFFFu, h1, 1));
            h1 = fmaxf(h1, __shfl_xor_sync(0xFFFFFFFFu, h1, 2));
            {
                float mn0 = fmaxf(mB0, h0), mn1 = fmaxf(mB1, h1);
                cB0 = fast_exp2(mB0 - mn0); cB1 = fast_exp2(mB1 - mn1);
                mB0 = mn0; mB1 = mn1;
            }
#define EXPROW(S, M0, M1) S##_0 = fast_exp2(S##_0 - M0); S##_1 = fast_exp2(S##_1 - M0); \
                          S##_2 = fast_exp2(S##_2 - M1); S##_3 = fast_exp2(S##_3 - M1);
            EXPROW(sA0, mA0, mA1) EXPROW(sA1, mA0, mA1) EXPROW(sA2, mA0, mA1) EXPROW(sA3, mA0, mA1)
            EXPROW(sB0, mB0, mB1) EXPROW(sB1, mB0, mB1) EXPROW(sB2, mB0, mB1) EXPROW(sB3, mB0, mB1)
#undef EXPROW
            {
                float r0 = ((sA0_0+sA0_1)+(sA1_0+sA1_1)) + ((sA2_0+sA2_1)+(sA3_0+sA3_1));
                float r1 = ((sA0_2+sA0_3)+(sA1_2+sA1_3)) + ((sA2_2+sA2_3)+(sA3_2+sA3_3));
                r0 += __shfl_xor_sync(0xFFFFFFFFu, r0, 1);
                r0 += __shfl_xor_sync(0xFFFFFFFFu, r0, 2);
                r1 += __shfl_xor_sync(0xFFFFFFFFu, r1, 1);
                r1 += __shfl_xor_sync(0xFFFFFFFFu, r1, 2);
                lA0 = lA0 * cA0 + r0; lA1 = lA1 * cA1 + r1;
                r0 = ((sB0_0+sB0_1)+(sB1_0+sB1_1)) + ((sB2_0+sB2_1)+(sB3_0+sB3_1));
                r1 = ((sB0_2+sB0_3)+(sB1_2+sB1_3)) + ((sB2_2+sB2_3)+(sB3_2+sB3_3));
                r0 += __shfl_xor_sync(0xFFFFFFFFu, r0, 1);
                r0 += __shfl_xor_sync(0xFFFFFFFFu, r0, 2);
                r1 += __shfl_xor_sync(0xFFFFFFFFu, r1, 1);
                r1 += __shfl_xor_sync(0xFFFFFFFFu, r1, 2);
                lB0 = lB0 * cB0 + r0; lB1 = lB1 * cB1 + r1;
            }
#define OSC(M, JO) o##M##JO##_0 *= c##M##0; o##M##JO##_1 *= c##M##0; \
                   o##M##JO##_2 *= c##M##1; o##M##JO##_3 *= c##M##1;
            OSC(A,0) OSC(A,1) OSC(A,2) OSC(A,3) OSC(B,0) OSC(B,1) OSC(B,2) OSC(B,3)
#undef OSC

            // --- PV ---
            unsigned pa0,pa1,pa2,pa3, pb0,pb1,pb2,pb3;
#define PV_JO(JO, VADDR) do { unsigned v0, v1; LDSMX2T(v0, v1, (VADDR));       \
            MMA(oA##JO##_0,oA##JO##_1,oA##JO##_2,oA##JO##_3, pa0,pa1,pa2,pa3, v0,v1); \
            MMA(oB##JO##_0,oB##JO##_1,oB##JO##_2,oB##JO##_3, pb0,pb1,pb2,pb3, v0,v1); \
        } while (0)
            // t = 0 (keys c32+0..15 -> S ntiles 0,1)
            H2(pa0, sA0_0, sA0_1); H2(pa1, sA0_2, sA0_3);
            H2(pa2, sA1_0, sA1_1); H2(pa3, sA1_2, sA1_3);
            H2(pb0, sB0_0, sB0_1); H2(pb1, sB0_2, sB0_3);
            H2(pb2, sB1_0, sB1_1); H2(pb3, sB1_2, sB1_3);
            PV_JO(0, vA + 0);  PV_JO(1, vA + 16);
            PV_JO(2, vA + 32); PV_JO(3, vA + 48);
            // t = 1 (keys c32+16..31 -> S ntiles 2,3)
            H2(pa0, sA2_0, sA2_1); H2(pa1, sA2_2, sA2_3);
            H2(pa2, sA3_0, sA3_1); H2(pa3, sA3_2, sA3_3);
            H2(pb0, sB2_0, sB2_1); H2(pb1, sB2_2, sB2_3);
            H2(pb2, sB3_0, sB3_1); H2(pb3, sB3_2, sB3_3);
            PV_JO(0, vA + 1280);      PV_JO(1, vA + 1280 + 16);
            PV_JO(2, vA + 1280 + 32); PV_JO(3, vA + 1280 + 48);
#undef PV_JO
        }
    }

    // ---- normalize + store o (fp16) to g_o[n][c=cph*8+head][hw=query] ----
    {
        const float iA0 = 1.f / lA0, iA1 = 1.f / lA1;
        const float iB0 = 1.f / lB0, iB1 = 1.f / lB1;
        const int qr0A = w * 32 + (l >> 2);
        const size_t gb = (size_t)n * (CC * HW);
        const int c2l = (l & 3) * 2;
#define ST_O(M, JO, QR0, I0, I1)                                               \
        {                                                                      \
            int ch0 = (JO)*8 + c2l;                                            \
            g_o[gb + (size_t)(ch0*8 + head)*256 + (QR0)]     = __float2half(o##M##JO##_0 * I0); \
            g_o[gb + (size_t)((ch0+1)*8 + head)*256 + (QR0)] = __float2half(o##M##JO##_1 * I0); \
            g_o[gb + (size_t)(ch0*8 + head)*256 + (QR0) + 8]     = __float2half(o##M##JO##_2 * I1); \
            g_o[gb + (size_t)((ch0+1)*8 + head)*256 + (QR0) + 8] = __float2half(o##M##JO##_3 * I1); \
        }
        ST_O(A,0, qr0A, iA0, iA1) ST_O(A,1, qr0A, iA0, iA1)
        ST_O(A,2, qr0A, iA0, iA1) ST_O(A,3, qr0A, iA0, iA1)
        ST_O(B,0, qr0A + 16, iB0, iB1) ST_O(B,1, qr0A + 16, iB0, iB1)
        ST_O(B,2, qr0A + 16, iB0, iB1) ST_O(B,3, qr0A + 16, iB0, iB1)
#undef ST_O
    }
}

// ---------------------------------------------------------------------------
// out_proj: out[n][oc][hw] = sum_c o[n][c][hw] * w_out[oc][c] + b_out[oc]
// A = g_o (fp16), tiled 64x64x16, 4x4 per thread.
// ---------------------------------------------------------------------------
__global__ __launch_bounds__(256, 1)
void out_proj(const float* __restrict__ w_out,
              const float* __restrict__ b_out,
              float* __restrict__ out)
{
    __shared__ __align__(16) float As[16][64];
    __shared__ __align__(16) float Bs[16][72];

    const int tid = threadIdx.x;
    const int tx = tid & 15;
    const int ty = tid >> 4;

    const int m0  = blockIdx.x * 64;
    const int nn  = m0 >> 8;
    const int hwb = m0 & 255;
    const int o0  = blockIdx.y * 64;

    const __half* Ab = g_o + (size_t)nn * CC * HW + hwb;

    const int am = tid & 63;
    const int ac = tid >> 6;
    const int boo = tid >> 2;
    const int bc4 = (tid & 3) * 4;

    float c00=0.f,c01=0.f,c02=0.f,c03=0.f;
    float c10=0.f,c11=0.f,c12=0.f,c13=0.f;
    float c20=0.f,c21=0.f,c22=0.f,c23=0.f;
    float c30=0.f,c31=0.f,c32=0.f,c33=0.f;

    for (int k0 = 0; k0 < CC; k0 += 16) {
        As[ac +  0][am] = __half2float(Ab[(size_t)(k0 + ac +  0) * HW + am]);
        As[ac +  4][am] = __half2float(Ab[(size_t)(k0 + ac +  4) * HW + am]);
        As[ac +  8][am] = __half2float(Ab[(size_t)(k0 + ac +  8) * HW + am]);
        As[ac + 12][am] = __half2float(Ab[(size_t)(k0 + ac + 12) * HW + am]);
        {
            float4 wv = *(const float4*)&w_out[(size_t)(o0 + boo) * CC + k0 + bc4];
            Bs[bc4 + 0][boo] = wv.x;
            Bs[bc4 + 1][boo] = wv.y;
            Bs[bc4 + 2][boo] = wv.z;
            Bs[bc4 + 3][boo] = wv.w;
        }
        __syncthreads();
#pragma unroll
        for (int k = 0; k < 16; k++) {
            float4 a4 = *(const float4*)&As[k][tx * 4];
            float4 b4 = *(const float4*)&Bs[k][ty * 4];
            c00 = fmaf(a4.x, b4.x, c00); c01 = fmaf(a4.x, b4.y, c01);
            c02 = fmaf(a4.x, b4.z, c02); c03 = fmaf(a4.x, b4.w, c03);
            c10 = fmaf(a4.y, b4.x, c10); c11 = fmaf(a4.y, b4.y, c11);
            c12 = fmaf(a4.y, b4.z, c12); c13 = fmaf(a4.y, b4.w, c13);
            c20 = fmaf(a4.z, b4.x, c20); c21 = fmaf(a4.z, b4.y, c21);
            c22 = fmaf(a4.z, b4.z, c22); c23 = fmaf(a4.z, b4.w, c23);
            c30 = fmaf(a4.w, b4.x, c30); c31 = fmaf(a4.w, b4.y, c31);
            c32 = fmaf(a4.w, b4.z, c32); c33 = fmaf(a4.w, b4.w, c33);
        }
        __syncthreads();
    }

#define OUT_EPI(J, A0, A1, A2, A3)                                             \
    {                                                                          \
        int o = o0 + ty * 4 + (J);                                             \
        float bb = b_out[o];                                                   \
        float4 st;                                                             \
        st.x = (A0) + bb; st.y = (A1) + bb; st.z = (A2) + bb; st.w = (A3) + bb;\
        *(float4*)&out[((size_t)nn * CC + o) * HW + hwb + tx * 4] = st;        \
    }
    OUT_EPI(0, c00, c10, c20, c30)
    OUT_EPI(1, c01, c11, c21, c31)
    OUT_EPI(2, c02, c12, c22, c32)
    OUT_EPI(3, c03, c13, c23, c33)
#undef OUT_EPI
}

// ---------------------------------------------------------------------------
extern "C" void kernel_launch(void* const* d_in, const int* in_sizes, int n_in,
                              void* d_out, int out_size)
{
    const float* x      = (const float*)d_in[0];
    const float* w_qkv  = (const float*)d_in[1];
    const float* b_qkv  = (const float*)d_in[2];
    const float* w_out  = (const float*)d_in[3];
    const float* b_out  = (const float*)d_in[4];
    const int*   access = (const int*)d_in[5];
    float* out = (float*)d_out;

    {
        dim3 grid(NT * HW / 64, 512 / 64);    // 208 x 8
        kv_proj<<<grid, 256>>>(x, w_qkv, b_qkv);
    }
    attn_tc<<<NT * NHEAD, 256>>>(x, w_qkv, b_qkv, access);
    {
        dim3 grid(NT * HW / 64, CC / 64);     // 208 x 4
        out_proj<<<grid, 256>>>(w_out, b_out, out);
    }
}

// round 15
// speedup vs baseline: 4.7357x; 1.0937x over previous
#include <cuda_runtime.h>
#include <cuda_fp16.h>
#include <math.h>

// Problem constants
#define TT 26
#define NB 2
#define NT (NB*TT)      // 52 frames
#define CC 256
#define HW 256          // 16*16
#define NHEAD 8
#define CPH 32          // C / NHEAD

// fp16 caches, head-major: [((n*8+head)*256 + hw)*32 + cph]
__device__ __half g_q[(size_t)NT * NHEAD * HW * CPH];   // 6.8 MB (pre-scaled)
__device__ __half g_k[(size_t)NT * NHEAD * HW * CPH];   // 6.8 MB
__device__ __half g_v[(size_t)NT * NHEAD * HW * CPH];   // 6.8 MB
// fp16 attention output, projection layout: [n][c=cph*8+head][hw]
__device__ __half g_o[(size_t)NT * CC * HW];            // 6.8 MB

// Fast 2^x on the FMA pipe (x <= 0).
__device__ __forceinline__ float fast_exp2(float x) {
    float y = fmaxf(x, -126.0f);
    float fn = y + 12582912.0f;
    int n = __float_as_int(fn) - 0x4B400000;
    float r = y - (fn - 12582912.0f);
    float p = 1.3333558146e-3f;
    p = fmaf(p, r, 9.6181291794e-3f);
    p = fmaf(p, r, 5.5504108664e-2f);
    p = fmaf(p, r, 2.4022650696e-1f);
    p = fmaf(p, r, 6.9314718056e-1f);
    p = fmaf(p, r, 1.0f);
    return p * __int_as_float((n + 127) << 23);
}

// ---- PTX wrappers -------------------------------------------------------
#define LDSMX2(R0, R1, ADDR) \
    asm volatile("ldmatrix.sync.aligned.m8n8.x2.shared.b16 {%0,%1},[%2];" \
                 : "=r"(R0), "=r"(R1) : "r"(ADDR))
#define LDSMX2T(R0, R1, ADDR) \
    asm volatile("ldmatrix.sync.aligned.m8n8.x2.trans.shared.b16 {%0,%1},[%2];" \
                 : "=r"(R0), "=r"(R1) : "r"(ADDR))
#define LDSMX4(R0, R1, R2, R3, ADDR) \
    asm volatile("ldmatrix.sync.aligned.m8n8.x4.shared.b16 {%0,%1,%2,%3},[%4];" \
                 : "=r"(R0), "=r"(R1), "=r"(R2), "=r"(R3) : "r"(ADDR))
#define MMA(C0, C1, C2, C3, A0, A1, A2, A3, B0, B1) \
    asm volatile("mma.sync.aligned.m16n8k16.row.col.f32.f16.f16.f32 " \
                 "{%0,%1,%2,%3},{%4,%5,%6,%7},{%8,%9},{%0,%1,%2,%3};" \
                 : "+f"(C0), "+f"(C1), "+f"(C2), "+f"(C3) \
                 : "r"(A0), "r"(A1), "r"(A2), "r"(A3), "r"(B0), "r"(B1))
#define H2(U, LO, HI) \
    asm("cvt.rn.f16x2.f32 %0,%1,%2;" : "=r"(U) : "f"(HI), "f"(LO))

// ---------------------------------------------------------------------------
// proj_gemm<MODE>: 128x128x16 tile, 256 threads, 8x8 micro-tile.
// MODE 0 (qkv): A = x (fp32), N=768; epilogue scatters fp16 into g_q/g_k/g_v
//   (q pre-scaled by (1/sqrt(32))*log2e).
// MODE 1 (out): A = g_o (fp16), N=256; epilogue float4 stores +bias to out.
// ---------------------------------------------------------------------------
template <int MODE>
__global__ __launch_bounds__(256, 1)
void proj_gemm(const float* __restrict__ xA,
               const float* __restrict__ W,
               const float* __restrict__ bias,
               float* __restrict__ out)
{
    __shared__ __align__(16) float As[16][128];
    __shared__ __align__(16) float Bs[16][136];

    const int tid = threadIdx.x;
    const int tx = tid & 15;
    const int ty = tid >> 4;

    const int m0  = blockIdx.x * 128;
    const int nn  = m0 >> 8;
    const int hwb = m0 & 255;          // 0 or 128
    const int o0  = blockIdx.y * 128;

    const int am = tid & 127;
    const int ac = tid >> 7;
    const int boo = tid >> 2;
    const int bc4 = (tid & 3) * 4;

    const float* Af = xA + (size_t)nn * CC * HW + hwb;           // MODE 0
    const __half* Ah = g_o + (size_t)nn * CC * HW + hwb;         // MODE 1

#define ACC8(I) float c##I##0=0.f,c##I##1=0.f,c##I##2=0.f,c##I##3=0.f, \
                      c##I##4=0.f,c##I##5=0.f,c##I##6=0.f,c##I##7=0.f;
    ACC8(0) ACC8(1) ACC8(2) ACC8(3) ACC8(4) ACC8(5) ACC8(6) ACC8(7)
#undef ACC8

    for (int k0 = 0; k0 < CC; k0 += 16) {
#pragma unroll
        for (int i = 0; i < 8; i++) {
            int c = ac + 2 * i;
            if (MODE == 0)
                As[c][am] = Af[(size_t)(k0 + c) * HW + am];
            else
                As[c][am] = __half2float(Ah[(size_t)(k0 + c) * HW + am]);
        }
        {
            float4 wv = *(const float4*)&W[(size_t)(o0 + boo) * CC + k0 + bc4];
            Bs[bc4 + 0][boo] = wv.x; Bs[bc4 + 1][boo] = wv.y;
            Bs[bc4 + 2][boo] = wv.z; Bs[bc4 + 3][boo] = wv.w;
            wv = *(const float4*)&W[(size_t)(o0 + boo + 64) * CC + k0 + bc4];
            Bs[bc4 + 0][boo + 64] = wv.x; Bs[bc4 + 1][boo + 64] = wv.y;
            Bs[bc4 + 2][boo + 64] = wv.z; Bs[bc4 + 3][boo + 64] = wv.w;
        }
        __syncthreads();

#pragma unroll
        for (int k = 0; k < 16; k++) {
            float4 a4a = *(const float4*)&As[k][tx * 4];
            float4 a4b = *(const float4*)&As[k][tx * 4 + 64];
            float4 b4a = *(const float4*)&Bs[k][ty * 4];
            float4 b4b = *(const float4*)&Bs[k][ty * 4 + 64];
#define FMAS(I, AV) \
            c##I##0 = fmaf(AV, b4a.x, c##I##0); c##I##1 = fmaf(AV, b4a.y, c##I##1); \
            c##I##2 = fmaf(AV, b4a.z, c##I##2); c##I##3 = fmaf(AV, b4a.w, c##I##3); \
            c##I##4 = fmaf(AV, b4b.x, c##I##4); c##I##5 = fmaf(AV, b4b.y, c##I##5); \
            c##I##6 = fmaf(AV, b4b.z, c##I##6); c##I##7 = fmaf(AV, b4b.w, c##I##7);
            FMAS(0, a4a.x) FMAS(1, a4a.y) FMAS(2, a4a.z) FMAS(3, a4a.w)
            FMAS(4, a4b.x) FMAS(5, a4b.y) FMAS(6, a4b.z) FMAS(7, a4b.w)
#undef FMAS
        }
        __syncthreads();
    }

    if (MODE == 0) {
        const float qscale = 0.17677669529663687f * 1.4426950408889634f;
#define QKV_EPI(J, JOFF, V0, V1, V2, V3, V4, V5, V6, V7)                       \
        {                                                                      \
            int o = o0 + ty * 4 + (J) + (JOFF);                                \
            float bb = bias[o];                                                \
            int part = o >> 8;                                                 \
            int c = o & 255;                                                   \
            int head = c & 7;                                                  \
            int cph  = c >> 3;                                                 \
            __half* dst = (part == 0) ? g_q : (part == 1) ? g_k : g_v;         \
            float sc = (part == 0) ? qscale : 1.0f;                            \
            __half* dp = dst + (((size_t)nn * 8 + head) * 256 + hwb + tx * 4) * 32 + cph; \
            dp[0]    = __float2half(((V0) + bb) * sc);                         \
            dp[32]   = __float2half(((V1) + bb) * sc);                         \
            dp[64]   = __float2half(((V2) + bb) * sc);                         \
            dp[96]   = __float2half(((V3) + bb) * sc);                         \
            dp[2048] = __float2half(((V4) + bb) * sc);                         \
            dp[2080] = __float2half(((V5) + bb) * sc);                         \
            dp[2112] = __float2half(((V6) + bb) * sc);                         \
            dp[2144] = __float2half(((V7) + bb) * sc);                         \
        }
        QKV_EPI(0,  0, c00, c10, c20, c30, c40, c50, c60, c70)
        QKV_EPI(1,  0, c01, c11, c21, c31, c41, c51, c61, c71)
        QKV_EPI(2,  0, c02, c12, c22, c32, c42, c52, c62, c72)
        QKV_EPI(3,  0, c03, c13, c23, c33, c43, c53, c63, c73)
        QKV_EPI(0, 64, c04, c14, c24, c34, c44, c54, c64, c74)
        QKV_EPI(1, 64, c05, c15, c25, c35, c45, c55, c65, c75)
        QKV_EPI(2, 64, c06, c16, c26, c36, c46, c56, c66, c76)
        QKV_EPI(3, 64, c07, c17, c27, c37, c47, c57, c67, c77)
#undef QKV_EPI
    } else {
#define OUT_EPI(J, JOFF, V0, V1, V2, V3, V4, V5, V6, V7)                       \
        {                                                                      \
            int o = o0 + ty * 4 + (J) + (JOFF);                                \
            float bb = bias[o];                                                \
            float4 st;                                                         \
            st.x = (V0) + bb; st.y = (V1) + bb; st.z = (V2) + bb; st.w = (V3) + bb; \
            *(float4*)&out[((size_t)nn * CC + o) * HW + hwb + tx * 4] = st;    \
            st.x = (V4) + bb; st.y = (V5) + bb; st.z = (V6) + bb; st.w = (V7) + bb; \
            *(float4*)&out[((size_t)nn * CC + o) * HW + hwb + tx * 4 + 64] = st; \
        }
        OUT_EPI(0,  0, c00, c10, c20, c30, c40, c50, c60, c70)
        OUT_EPI(1,  0, c01, c11, c21, c31, c41, c51, c61, c71)
        OUT_EPI(2,  0, c02, c12, c22, c32, c42, c52, c62, c72)
        OUT_EPI(3,  0, c03, c13, c23, c33, c43, c53, c63, c73)
        OUT_EPI(0, 64, c04, c14, c24, c34, c44, c54, c64, c74)
        OUT_EPI(1, 64, c05, c15, c25, c35, c45, c55, c65, c75)
        OUT_EPI(2, 64, c06, c16, c26, c36, c46, c56, c66, c76)
        OUT_EPI(3, 64, c07, c17, c27, c37, c47, c57, c67, c77)
#undef OUT_EPI
    }
}

// ---------------------------------------------------------------------------
// Tensor-core flash attention. One block per (frame n, head); 256 threads.
// Q loaded from g_q (pre-scaled); mainloop identical to proven R13 code.
// ---------------------------------------------------------------------------
__global__ __launch_bounds__(256, 1)
void attn_tc(const int* __restrict__ access)
{
    // Halves: Qs[256][40] @0, Ks[128][40] @10240, Vs[128][40] @15360
    __shared__ __align__(16) __half sm_h[20480];

    const int tid  = threadIdx.x;
    const int w    = tid >> 5;
    const int l    = tid & 31;
    const int bid  = blockIdx.x;
    const int n    = bid >> 3;
    const int head = bid & 7;
    const int t    = n % TT;
    const int b_   = n / TT;

    unsigned sbase;
    asm("{ .reg .u64 t0; cvta.to.shared.u64 t0, %1; cvt.u32.u64 %0, t0; }"
        : "=r"(sbase) : "l"(sm_h));
    const unsigned qs_u = sbase;
    const unsigned ks_u = sbase + 20480;
    const unsigned vs_u = sbase + 30720;

    // ---- Load Q tile (256 rows x 32 halves = 1024 uint4; 4 per thread) ----
    {
        const size_t qbase = ((size_t)n * 8 + head) * (size_t)(HW * CPH);
#pragma unroll
        for (int u = 0; u < 4; u++) {
            int lin = tid * 4 + u;            // 0..1023
            int row = lin >> 2, cb16 = (lin & 3) * 16;
            uint4 rq = *((const uint4*)(g_q + qbase) + lin);
            *(uint4*)((char*)sm_h + row * 80 + cb16) = rq;
        }
    }
    __syncthreads();

    // ---- Load Q a-frags (persist in registers) ----
    unsigned aqA0_0,aqA0_1,aqA0_2,aqA0_3, aqA1_0,aqA1_1,aqA1_2,aqA1_3;
    unsigned aqB0_0,aqB0_1,aqB0_2,aqB0_3, aqB1_0,aqB1_1,aqB1_2,aqB1_3;
    {
        unsigned qrow = qs_u + (w * 32 + (l & 15)) * 80 + (l >> 4) * 16;
        LDSMX4(aqA0_0,aqA0_1,aqA0_2,aqA0_3, qrow);
        LDSMX4(aqA1_0,aqA1_1,aqA1_2,aqA1_3, qrow + 32);
        LDSMX4(aqB0_0,aqB0_1,aqB0_2,aqB0_3, qrow + 16*80);
        LDSMX4(aqB1_0,aqB1_1,aqB1_2,aqB1_3, qrow + 16*80 + 32);
    }

    const unsigned k_lane = ks_u + (l & 7) * 80 + ((l >> 3) & 1) * 16;
    const unsigned v_lane = vs_u + (l & 15) * 80;

    float mA0 = -1e30f, mA1 = -1e30f, mB0 = -1e30f, mB1 = -1e30f;
    float lA0 = 0.f, lA1 = 0.f, lB0 = 0.f, lB1 = 0.f;
    float oA0_0=0.f,oA0_1=0.f,oA0_2=0.f,oA0_3=0.f, oA1_0=0.f,oA1_1=0.f,oA1_2=0.f,oA1_3=0.f;
    float oA2_0=0.f,oA2_1=0.f,oA2_2=0.f,oA2_3=0.f, oA3_0=0.f,oA3_1=0.f,oA3_2=0.f,oA3_3=0.f;
    float oB0_0=0.f,oB0_1=0.f,oB0_2=0.f,oB0_3=0.f, oB1_0=0.f,oB1_1=0.f,oB1_2=0.f,oB1_3=0.f;
    float oB2_0=0.f,oB2_1=0.f,oB2_2=0.f,oB2_3=0.f, oB3_0=0.f,oB3_1=0.f,oB3_2=0.f,oB3_3=0.f;

    for (int tt = 0; tt < 8; tt++) {
        const int f  = access[t * 4 + (tt >> 1)];
        const int nf = b_ * TT + f;
        const size_t kvbase = (((size_t)nf * 8 + head) * 256 + (tt & 1) * 128) * 32;

        __syncthreads();
        {
#pragma unroll
            for (int u = 0; u < 2; u++) {
                int lin = tid * 2 + u;
                int row = lin >> 2, cb16 = (lin & 3) * 16;
                uint4 rk = *((const uint4*)(g_k + kvbase) + lin);
                *(uint4*)((char*)sm_h + 20480 + row * 80 + cb16) = rk;
                uint4 rv = *((const uint4*)(g_v + kvbase) + lin);
                *(uint4*)((char*)sm_h + 30720 + row * 80 + cb16) = rv;
            }
        }
        __syncthreads();

#pragma unroll
        for (int cc = 0; cc < 4; cc++) {
            const int c32 = cc * 32;
            const unsigned kA = k_lane + c32 * 80;
            const unsigned vA = v_lane + c32 * 80;

            float sA0_0=0.f,sA0_1=0.f,sA0_2=0.f,sA0_3=0.f, sA1_0=0.f,sA1_1=0.f,sA1_2=0.f,sA1_3=0.f;
            float sA2_0=0.f,sA2_1=0.f,sA2_2=0.f,sA2_3=0.f, sA3_0=0.f,sA3_1=0.f,sA3_2=0.f,sA3_3=0.f;
            float sB0_0=0.f,sB0_1=0.f,sB0_2=0.f,sB0_3=0.f, sB1_0=0.f,sB1_1=0.f,sB1_2=0.f,sB1_3=0.f;
            float sB2_0=0.f,sB2_1=0.f,sB2_2=0.f,sB2_3=0.f, sB3_0=0.f,sB3_1=0.f,sB3_2=0.f,sB3_3=0.f;

#define QK_NT(J) do { unsigned b0,b1,b2,b3;                                    \
            LDSMX2(b0, b1, kA + (J)*640);                                      \
            LDSMX2(b2, b3, kA + (J)*640 + 32);                                 \
            MMA(sA##J##_0,sA##J##_1,sA##J##_2,sA##J##_3, aqA0_0,aqA0_1,aqA0_2,aqA0_3, b0,b1); \
            MMA(sA##J##_0,sA##J##_1,sA##J##_2,sA##J##_3, aqA1_0,aqA1_1,aqA1_2,aqA1_3, b2,b3); \
            MMA(sB##J##_0,sB##J##_1,sB##J##_2,sB##J##_3, aqB0_0,aqB0_1,aqB0_2,aqB0_3, b0,b1); \
            MMA(sB##J##_0,sB##J##_1,sB##J##_2,sB##J##_3, aqB1_0,aqB1_1,aqB1_2,aqB1_3, b2,b3); \
        } while (0)
            QK_NT(0); QK_NT(1); QK_NT(2); QK_NT(3);
#undef QK_NT

            float h0, h1, cA0, cA1, cB0, cB1;
            h0 = fmaxf(fmaxf(fmaxf(sA0_0,sA0_1),fmaxf(sA1_0,sA1_1)),
                       fmaxf(fmaxf(sA2_0,sA2_1),fmaxf(sA3_0,sA3_1)));
            h1 = fmaxf(fmaxf(fmaxf(sA0_2,sA0_3),fmaxf(sA1_2,sA1_3)),
                       fmaxf(fmaxf(sA2_2,sA2_3),fmaxf(sA3_2,sA3_3)));
            h0 = fmaxf(h0, __shfl_xor_sync(0xFFFFFFFFu, h0, 1));
            h0 = fmaxf(h0, __shfl_xor_sync(0xFFFFFFFFu, h0, 2));
            h1 = fmaxf(h1, __shfl_xor_sync(0xFFFFFFFFu, h1, 1));
            h1 = fmaxf(h1, __shfl_xor_sync(0xFFFFFFFFu, h1, 2));
            {
                float mn0 = fmaxf(mA0, h0), mn1 = fmaxf(mA1, h1);
                cA0 = fast_exp2(mA0 - mn0); cA1 = fast_exp2(mA1 - mn1);
                mA0 = mn0; mA1 = mn1;
            }
            h0 = fmaxf(fmaxf(fmaxf(sB0_0,sB0_1),fmaxf(sB1_0,sB1_1)),
                       fmaxf(fmaxf(sB2_0,sB2_1),fmaxf(sB3_0,sB3_1)));
            h1 = fmaxf(fmaxf(fmaxf(sB0_2,sB0_3),fmaxf(sB1_2,sB1_3)),
                       fmaxf(fmaxf(sB2_2,sB2_3),fmaxf(sB3_2,sB3_3)));
            h0 = fmaxf(h0, __shfl_xor_sync(0xFFFFFFFFu, h0, 1));
            h0 = fmaxf(h0, __shfl_xor_sync(0xFFFFFFFFu, h0, 2));
            h1 = fmaxf(h1, __shfl_xor_sync(0xFFFFFFFFu, h1, 1));
            h1 = fmaxf(h1, __shfl_xor_sync(0xFFFFFFFFu, h1, 2));
            {
                float mn0 = fmaxf(mB0, h0), mn1 = fmaxf(mB1, h1);
                cB0 = fast_exp2(mB0 - mn0); cB1 = fast_exp2(mB1 - mn1);
                mB0 = mn0; mB1 = mn1;
            }
#define EXPROW(S, M0, M1) S##_0 = fast_exp2(S##_0 - M0); S##_1 = fast_exp2(S##_1 - M0); \
                          S##_2 = fast_exp2(S##_2 - M1); S##_3 = fast_exp2(S##_3 - M1);
            EXPROW(sA0, mA0, mA1) EXPROW(sA1, mA0, mA1) EXPROW(sA2, mA0, mA1) EXPROW(sA3, mA0, mA1)
            EXPROW(sB0, mB0, mB1) EXPROW(sB1, mB0, mB1) EXPROW(sB2, mB0, mB1) EXPROW(sB3, mB0, mB1)
#undef EXPROW
            {
                float r0 = ((sA0_0+sA0_1)+(sA1_0+sA1_1)) + ((sA2_0+sA2_1)+(sA3_0+sA3_1));
                float r1 = ((sA0_2+sA0_3)+(sA1_2+sA1_3)) + ((sA2_2+sA2_3)+(sA3_2+sA3_3));
                r0 += __shfl_xor_sync(0xFFFFFFFFu, r0, 1);
                r0 += __shfl_xor_sync(0xFFFFFFFFu, r0, 2);
                r1 += __shfl_xor_sync(0xFFFFFFFFu, r1, 1);
                r1 += __shfl_xor_sync(0xFFFFFFFFu, r1, 2);
                lA0 = lA0 * cA0 + r0; lA1 = lA1 * cA1 + r1;
                r0 = ((sB0_0+sB0_1)+(sB1_0+sB1_1)) + ((sB2_0+sB2_1)+(sB3_0+sB3_1));
                r1 = ((sB0_2+sB0_3)+(sB1_2+sB1_3)) + ((sB2_2+sB2_3)+(sB3_2+sB3_3));
                r0 += __shfl_xor_sync(0xFFFFFFFFu, r0, 1);
                r0 += __shfl_xor_sync(0xFFFFFFFFu, r0, 2);
                r1 += __shfl_xor_sync(0xFFFFFFFFu, r1, 1);
                r1 += __shfl_xor_sync(0xFFFFFFFFu, r1, 2);
                lB0 = lB0 * cB0 + r0; lB1 = lB1 * cB1 + r1;
            }
#define OSC(M, JO) o##M##JO##_0 *= c##M##0; o##M##JO##_1 *= c##M##0; \
                   o##M##JO##_2 *= c##M##1; o##M##JO##_3 *= c##M##1;
            OSC(A,0) OSC(A,1) OSC(A,2) OSC(A,3) OSC(B,0) OSC(B,1) OSC(B,2) OSC(B,3)
#undef OSC

            unsigned pa0,pa1,pa2,pa3, pb0,pb1,pb2,pb3;
#define PV_JO(JO, VADDR) do { unsigned v0, v1; LDSMX2T(v0, v1, (VADDR));       \
            MMA(oA##JO##_0,oA##JO##_1,oA##JO##_2,oA##JO##_3, pa0,pa1,pa2,pa3, v0,v1); \
            MMA(oB##JO##_0,oB##JO##_1,oB##JO##_2,oB##JO##_3, pb0,pb1,pb2,pb3, v0,v1); \
        } while (0)
            H2(pa0, sA0_0, sA0_1); H2(pa1, sA0_2, sA0_3);
            H2(pa2, sA1_0, sA1_1); H2(pa3, sA1_2, sA1_3);
            H2(pb0, sB0_0, sB0_1); H2(pb1, sB0_2, sB0_3);
            H2(pb2, sB1_0, sB1_1); H2(pb3, sB1_2, sB1_3);
            PV_JO(0, vA + 0);  PV_JO(1, vA + 16);
            PV_JO(2, vA + 32); PV_JO(3, vA + 48);
            H2(pa0, sA2_0, sA2_1); H2(pa1, sA2_2, sA2_3);
            H2(pa2, sA3_0, sA3_1); H2(pa3, sA3_2, sA3_3);
            H2(pb0, sB2_0, sB2_1); H2(pb1, sB2_2, sB2_3);
            H2(pb2, sB3_0, sB3_1); H2(pb3, sB3_2, sB3_3);
            PV_JO(0, vA + 1280);      PV_JO(1, vA + 1280 + 16);
            PV_JO(2, vA + 1280 + 32); PV_JO(3, vA + 1280 + 48);
#undef PV_JO
        }
    }

    // ---- normalize + store o (fp16) to g_o[n][c=cph*8+head][hw=query] ----
    {
        const float iA0 = 1.f / lA0, iA1 = 1.f / lA1;
        const float iB0 = 1.f / lB0, iB1 = 1.f / lB1;
        const int qr0A = w * 32 + (l >> 2);
        const size_t gb = (size_t)n * (CC * HW);
        const int c2l = (l & 3) * 2;
#define ST_O(M, JO, QR0, I0, I1)                                               \
        {                                                                      \
            int ch0 = (JO)*8 + c2l;                                            \
            g_o[gb + (size_t)(ch0*8 + head)*256 + (QR0)]     = __float2half(o##M##JO##_0 * I0); \
            g_o[gb + (size_t)((ch0+1)*8 + head)*256 + (QR0)] = __float2half(o##M##JO##_1 * I0); \
            g_o[gb + (size_t)(ch0*8 + head)*256 + (QR0) + 8]     = __float2half(o##M##JO##_2 * I1); \
            g_o[gb + (size_t)((ch0+1)*8 + head)*256 + (QR0) + 8] = __float2half(o##M##JO##_3 * I1); \
        }
        ST_O(A,0, qr0A, iA0, iA1) ST_O(A,1, qr0A, iA0, iA1)
        ST_O(A,2, qr0A, iA0, iA1) ST_O(A,3, qr0A, iA0, iA1)
        ST_O(B,0, qr0A + 16, iB0, iB1) ST_O(B,1, qr0A + 16, iB0, iB1)
        ST_O(B,2, qr0A + 16, iB0, iB1) ST_O(B,3, qr0A + 16, iB0, iB1)
#undef ST_O
    }
}

// ---------------------------------------------------------------------------
extern "C" void kernel_launch(void* const* d_in, const int* in_sizes, int n_in,
                              void* d_out, int out_size)
{
    const float* x      = (const float*)d_in[0];
    const float* w_qkv  = (const float*)d_in[1];
    const float* b_qkv  = (const float*)d_in[2];
    const float* w_out  = (const float*)d_in[3];
    const float* b_out  = (const float*)d_in[4];
    const int*   access = (const int*)d_in[5];
    float* out = (float*)d_out;

    {
        dim3 grid(NT * HW / 128, 768 / 128);   // 104 x 6
        proj_gemm<0><<<grid, 256>>>(x, w_qkv, b_qkv, nullptr);
    }
    attn_tc<<<NT * NHEAD, 256>>>(access);
    {
        dim3 grid(NT * HW / 128, 256 / 128);   // 104 x 2
        proj_gemm<1><<<grid, 256>>>(nullptr, w_out, b_out, out);
    }
}

// round 16
// speedup vs baseline: 7.2912x; 1.5396x over previous
#include <cuda_runtime.h>
#include <cuda_fp16.h>
#include <math.h>

// Problem constants
#define TT 26
#define NB 2
#define NT (NB*TT)      // 52 frames
#define CC 256
#define HW 256          // 16*16
#define NHEAD 8
#define CPH 32          // C / NHEAD

// fp16 caches, head-major: [((n*8+head)*256 + hw)*32 + cph]
__device__ __half g_q[(size_t)NT * NHEAD * HW * CPH];   // 6.8 MB (pre-scaled)
__device__ __half g_k[(size_t)NT * NHEAD * HW * CPH];   // 6.8 MB
__device__ __half g_v[(size_t)NT * NHEAD * HW * CPH];   // 6.8 MB
// fp16 attention output, projection layout: [n][c=cph*8+head][hw]
__device__ __half g_o[(size_t)NT * CC * HW];            // 6.8 MB
// fp16 weights
__device__ __half g_wh[768 * 256];                      // w_qkv fp16
__device__ __half g_woh[256 * 256];                     // w_out fp16

// Fast 2^x on the FMA pipe (x <= 0).
__device__ __forceinline__ float fast_exp2(float x) {
    float y = fmaxf(x, -126.0f);
    float fn = y + 12582912.0f;
    int n = __float_as_int(fn) - 0x4B400000;
    float r = y - (fn - 12582912.0f);
    float p = 1.3333558146e-3f;
    p = fmaf(p, r, 9.6181291794e-3f);
    p = fmaf(p, r, 5.5504108664e-2f);
    p = fmaf(p, r, 2.4022650696e-1f);
    p = fmaf(p, r, 6.9314718056e-1f);
    p = fmaf(p, r, 1.0f);
    return p * __int_as_float((n + 127) << 23);
}

// ---- PTX wrappers -------------------------------------------------------
#define LDSMX2(R0, R1, ADDR) \
    asm volatile("ldmatrix.sync.aligned.m8n8.x2.shared.b16 {%0,%1},[%2];" \
                 : "=r"(R0), "=r"(R1) : "r"(ADDR))
#define LDSMX2T(R0, R1, ADDR) \
    asm volatile("ldmatrix.sync.aligned.m8n8.x2.trans.shared.b16 {%0,%1},[%2];" \
                 : "=r"(R0), "=r"(R1) : "r"(ADDR))
#define LDSMX4(R0, R1, R2, R3, ADDR) \
    asm volatile("ldmatrix.sync.aligned.m8n8.x4.shared.b16 {%0,%1,%2,%3},[%4];" \
                 : "=r"(R0), "=r"(R1), "=r"(R2), "=r"(R3) : "r"(ADDR))
#define MMA(C0, C1, C2, C3, A0, A1, A2, A3, B0, B1) \
    asm volatile("mma.sync.aligned.m16n8k16.row.col.f32.f16.f16.f32 " \
                 "{%0,%1,%2,%3},{%4,%5,%6,%7},{%8,%9},{%0,%1,%2,%3};" \
                 : "+f"(C0), "+f"(C1), "+f"(C2), "+f"(C3) \
                 : "r"(A0), "r"(A1), "r"(A2), "r"(A3), "r"(B0), "r"(B1))
#define H2(U, LO, HI) \
    asm("cvt.rn.f16x2.f32 %0,%1,%2;" : "=r"(U) : "f"(HI), "f"(LO))

// ---------------------------------------------------------------------------
// convert_w: fp32 weights -> fp16 copies.
// ---------------------------------------------------------------------------
__global__ __launch_bounds__(256, 1)
void convert_w(const float* __restrict__ w_qkv, const float* __restrict__ w_out)
{
    int i = blockIdx.x * 256 + threadIdx.x;
    if (i < 768 * 256) g_wh[i] = __float2half(w_qkv[i]);
    if (i < 256 * 256) g_woh[i] = __float2half(w_out[i]);
}

// ---------------------------------------------------------------------------
// tc_gemm<MODE>: fp16 tensor-core GEMM, 128x128 block tile, K-chunk 32,
// 8 warps (warp tile 32m x 64n), mma m16n8k16 fp32-accum.
// MODE 0 (qkv): A = x fp32 (converted on stage), B = g_wh, N=768;
//   epilogue scatters fp16 into g_q (pre-scaled) / g_k / g_v.
// MODE 1 (out): A = g_o fp16, B = g_woh, N=256; fp32 +bias stores to out.
// ---------------------------------------------------------------------------
template <int MODE>
__global__ __launch_bounds__(256, 1)
void tc_gemm(const float* __restrict__ xA,
             const float* __restrict__ bias,
             float* __restrict__ out)
{
    __shared__ __align__(16) __half smA[128 * 40];   // [m][k], pitch 80 B
    __shared__ __align__(16) __half smB[128 * 40];   // [o][k], pitch 80 B

    const int tid = threadIdx.x;
    const int w   = tid >> 5;
    const int l   = tid & 31;
    const int wm  = w & 3;            // 4 M-subtiles of 32
    const int wn  = w >> 2;           // 2 N-subtiles of 64

    const int m0  = blockIdx.x * 128;
    const int nn  = m0 >> 8;
    const int hwb = m0 & 255;         // 0 or 128
    const int o0  = blockIdx.y * 128;

    unsigned As_u, Bs_u;
    asm("{ .reg .u64 t0; cvta.to.shared.u64 t0, %1; cvt.u32.u64 %0, t0; }"
        : "=r"(As_u) : "l"(smA));
    asm("{ .reg .u64 t0; cvta.to.shared.u64 t0, %1; cvt.u32.u64 %0, t0; }"
        : "=r"(Bs_u) : "l"(smB));

    // staging maps
    const int sm_m = tid & 127;       // A: local m
    const int sg   = tid >> 7;        // A: channel group (0..1) of 16
    const __half* Wh = (MODE == 0) ? g_wh : g_woh;
    const float*  Af = xA + (size_t)nn * CC * HW + hwb;            // MODE 0
    const __half* Ah = g_o + (size_t)nn * CC * HW + hwb;           // MODE 1

    // ldmatrix lane bases
    const unsigned a_lane = As_u + (wm * 32 + (l & 15)) * 80 + (l >> 4) * 16;
    const unsigned b_lane = Bs_u + (wn * 64 + (l & 7)) * 80 + ((l >> 3) & 1) * 16;

#define FOR_NT(F) F(0) F(1) F(2) F(3) F(4) F(5) F(6) F(7)
#define DEF_ACC(NT) float c0##NT##_0=0.f,c0##NT##_1=0.f,c0##NT##_2=0.f,c0##NT##_3=0.f, \
                          c1##NT##_0=0.f,c1##NT##_1=0.f,c1##NT##_2=0.f,c1##NT##_3=0.f;
    FOR_NT(DEF_ACC)
#undef DEF_ACC

    for (int k0 = 0; k0 < CC; k0 += 32) {
        // ---- stage A: 128 m x 32 k (fp16, half2 per store) ----
#pragma unroll
        for (int j = 0; j < 8; j++) {
            int c = sg * 16 + j * 2;
            __half2 hv;
            if (MODE == 0) {
                float a0 = Af[(size_t)(k0 + c) * HW + sm_m];
                float a1 = Af[(size_t)(k0 + c + 1) * HW + sm_m];
                unsigned u; H2(u, a0, a1);
                hv = *(__half2*)&u;
            } else {
                hv = __halves2half2(Ah[(size_t)(k0 + c) * HW + sm_m],
                                    Ah[(size_t)(k0 + c + 1) * HW + sm_m]);
            }
            *(__half2*)((char*)smA + sm_m * 80 + c * 2) = hv;
        }
        // ---- stage B: 128 o x 32 k (uint4) ----
#pragma unroll
        for (int u = 0; u < 2; u++) {
            int lin = tid * 2 + u;            // 0..511
            int row = lin >> 2;
            int cb  = (lin & 3) * 8;          // halves
            uint4 rv = *(const uint4*)(Wh + (size_t)(o0 + row) * 256 + k0 + cb);
            *(uint4*)((char*)smB + row * 80 + cb * 2) = rv;
        }
        __syncthreads();

#pragma unroll
        for (int ks = 0; ks < 2; ks++) {
            unsigned a00,a01,a02,a03, a10,a11,a12,a13;
            LDSMX4(a00,a01,a02,a03, a_lane + ks * 32);
            LDSMX4(a10,a11,a12,a13, a_lane + 1280 + ks * 32);
#define DO_NT(NT) { unsigned b0, b1; \
            LDSMX2(b0, b1, b_lane + (NT) * 640 + ks * 32); \
            MMA(c0##NT##_0,c0##NT##_1,c0##NT##_2,c0##NT##_3, a00,a01,a02,a03, b0,b1); \
            MMA(c1##NT##_0,c1##NT##_1,c1##NT##_2,c1##NT##_3, a10,a11,a12,a13, b0,b1); }
            FOR_NT(DO_NT)
#undef DO_NT
        }
        __syncthreads();
    }

    // ---- epilogue ----
    const int ocb = o0 + wn * 64 + (l & 3) * 2;
    const int rb  = hwb + wm * 32 + (l >> 2);

    if (MODE == 0) {
        const float qscale = 0.17677669529663687f * 1.4426950408889634f;
#define ST1(V, OC, HWV) { \
        int o_ = (OC); float bb = bias[o_]; int part = o_ >> 8; int ci = o_ & 255; \
        __half* dst = (part == 0) ? g_q : ((part == 1) ? g_k : g_v); \
        float sc = (part == 0) ? qscale : 1.0f; \
        dst[(((size_t)nn * 8 + (ci & 7)) * 256 + (HWV)) * 32 + (ci >> 3)] = \
            __float2half(((V) + bb) * sc); }
#define EPI0(NT) \
        ST1(c0##NT##_0, ocb + (NT)*8,     rb) \
        ST1(c0##NT##_1, ocb + (NT)*8 + 1, rb) \
        ST1(c0##NT##_2, ocb + (NT)*8,     rb + 8) \
        ST1(c0##NT##_3, ocb + (NT)*8 + 1, rb + 8) \
        ST1(c1##NT##_0, ocb + (NT)*8,     rb + 16) \
        ST1(c1##NT##_1, ocb + (NT)*8 + 1, rb + 16) \
        ST1(c1##NT##_2, ocb + (NT)*8,     rb + 24) \
        ST1(c1##NT##_3, ocb + (NT)*8 + 1, rb + 24)
        FOR_NT(EPI0)
#undef EPI0
#undef ST1
    } else {
#define ST1B(V, OC, HWV) \
        out[((size_t)nn * CC + (OC)) * HW + (HWV)] = (V) + bias[(OC)];
#define EPI1(NT) \
        ST1B(c0##NT##_0, ocb + (NT)*8,     rb) \
        ST1B(c0##NT##_1, ocb + (NT)*8 + 1, rb) \
        ST1B(c0##NT##_2, ocb + (NT)*8,     rb + 8) \
        ST1B(c0##NT##_3, ocb + (NT)*8 + 1, rb + 8) \
        ST1B(c1##NT##_0, ocb + (NT)*8,     rb + 16) \
        ST1B(c1##NT##_1, ocb + (NT)*8 + 1, rb + 16) \
        ST1B(c1##NT##_2, ocb + (NT)*8,     rb + 24) \
        ST1B(c1##NT##_3, ocb + (NT)*8 + 1, rb + 24)
        FOR_NT(EPI1)
#undef EPI1
#undef ST1B
    }
#undef FOR_NT
}

// ---------------------------------------------------------------------------
// Tensor-core flash attention (unchanged from R15, passing).
// ---------------------------------------------------------------------------
__global__ __launch_bounds__(256, 1)
void attn_tc(const int* __restrict__ access)
{
    __shared__ __align__(16) __half sm_h[20480];

    const int tid  = threadIdx.x;
    const int w    = tid >> 5;
    const int l    = tid & 31;
    const int bid  = blockIdx.x;
    const int n    = bid >> 3;
    const int head = bid & 7;
    const int t    = n % TT;
    const int b_   = n / TT;

    unsigned sbase;
    asm("{ .reg .u64 t0; cvta.to.shared.u64 t0, %1; cvt.u32.u64 %0, t0; }"
        : "=r"(sbase) : "l"(sm_h));
    const unsigned qs_u = sbase;
    const unsigned ks_u = sbase + 20480;
    const unsigned vs_u = sbase + 30720;

    {
        const size_t qbase = ((size_t)n * 8 + head) * (size_t)(HW * CPH);
#pragma unroll
        for (int u = 0; u < 4; u++) {
            int lin = tid * 4 + u;
            int row = lin >> 2, cb16 = (lin & 3) * 16;
            uint4 rq = *((const uint4*)(g_q + qbase) + lin);
            *(uint4*)((char*)sm_h + row * 80 + cb16) = rq;
        }
    }
    __syncthreads();

    unsigned aqA0_0,aqA0_1,aqA0_2,aqA0_3, aqA1_0,aqA1_1,aqA1_2,aqA1_3;
    unsigned aqB0_0,aqB0_1,aqB0_2,aqB0_3, aqB1_0,aqB1_1,aqB1_2,aqB1_3;
    {
        unsigned qrow = qs_u + (w * 32 + (l & 15)) * 80 + (l >> 4) * 16;
        LDSMX4(aqA0_0,aqA0_1,aqA0_2,aqA0_3, qrow);
        LDSMX4(aqA1_0,aqA1_1,aqA1_2,aqA1_3, qrow + 32);
        LDSMX4(aqB0_0,aqB0_1,aqB0_2,aqB0_3, qrow + 16*80);
        LDSMX4(aqB1_0,aqB1_1,aqB1_2,aqB1_3, qrow + 16*80 + 32);
    }

    const unsigned k_lane = ks_u + (l & 7) * 80 + ((l >> 3) & 1) * 16;
    const unsigned v_lane = vs_u + (l & 15) * 80;

    float mA0 = -1e30f, mA1 = -1e30f, mB0 = -1e30f, mB1 = -1e30f;
    float lA0 = 0.f, lA1 = 0.f, lB0 = 0.f, lB1 = 0.f;
    float oA0_0=0.f,oA0_1=0.f,oA0_2=0.f,oA0_3=0.f, oA1_0=0.f,oA1_1=0.f,oA1_2=0.f,oA1_3=0.f;
    float oA2_0=0.f,oA2_1=0.f,oA2_2=0.f,oA2_3=0.f, oA3_0=0.f,oA3_1=0.f,oA3_2=0.f,oA3_3=0.f;
    float oB0_0=0.f,oB0_1=0.f,oB0_2=0.f,oB0_3=0.f, oB1_0=0.f,oB1_1=0.f,oB1_2=0.f,oB1_3=0.f;
    float oB2_0=0.f,oB2_1=0.f,oB2_2=0.f,oB2_3=0.f, oB3_0=0.f,oB3_1=0.f,oB3_2=0.f,oB3_3=0.f;

    for (int tt = 0; tt < 8; tt++) {
        const int f  = access[t * 4 + (tt >> 1)];
        const int nf = b_ * TT + f;
        const size_t kvbase = (((size_t)nf * 8 + head) * 256 + (tt & 1) * 128) * 32;

        __syncthreads();
        {
#pragma unroll
            for (int u = 0; u < 2; u++) {
                int lin = tid * 2 + u;
                int row = lin >> 2, cb16 = (lin & 3) * 16;
                uint4 rk = *((const uint4*)(g_k + kvbase) + lin);
                *(uint4*)((char*)sm_h + 20480 + row * 80 + cb16) = rk;
                uint4 rv = *((const uint4*)(g_v + kvbase) + lin);
                *(uint4*)((char*)sm_h + 30720 + row * 80 + cb16) = rv;
            }
        }
        __syncthreads();

#pragma unroll
        for (int cc = 0; cc < 4; cc++) {
            const int c32 = cc * 32;
            const unsigned kA = k_lane + c32 * 80;
            const unsigned vA = v_lane + c32 * 80;

            float sA0_0=0.f,sA0_1=0.f,sA0_2=0.f,sA0_3=0.f, sA1_0=0.f,sA1_1=0.f,sA1_2=0.f,sA1_3=0.f;
            float sA2_0=0.f,sA2_1=0.f,sA2_2=0.f,sA2_3=0.f, sA3_0=0.f,sA3_1=0.f,sA3_2=0.f,sA3_3=0.f;
            float sB0_0=0.f,sB0_1=0.f,sB0_2=0.f,sB0_3=0.f, sB1_0=0.f,sB1_1=0.f,sB1_2=0.f,sB1_3=0.f;
            float sB2_0=0.f,sB2_1=0.f,sB2_2=0.f,sB2_3=0.f, sB3_0=0.f,sB3_1=0.f,sB3_2=0.f,sB3_3=0.f;

#define QK_NT(J) do { unsigned b0,b1,b2,b3;                                    \
            LDSMX2(b0, b1, kA + (J)*640);                                      \
            LDSMX2(b2, b3, kA + (J)*640 + 32);                                 \
            MMA(sA##J##_0,sA##J##_1,sA##J##_2,sA##J##_3, aqA0_0,aqA0_1,aqA0_2,aqA0_3, b0,b1); \
            MMA(sA##J##_0,sA##J##_1,sA##J##_2,sA##J##_3, aqA1_0,aqA1_1,aqA1_2,aqA1_3, b2,b3); \
            MMA(sB##J##_0,sB##J##_1,sB##J##_2,sB##J##_3, aqB0_0,aqB0_1,aqB0_2,aqB0_3, b0,b1); \
            MMA(sB##J##_0,sB##J##_1,sB##J##_2,sB##J##_3, aqB1_0,aqB1_1,aqB1_2,aqB1_3, b2,b3); \
        } while (0)
            QK_NT(0); QK_NT(1); QK_NT(2); QK_NT(3);
#undef QK_NT

            float h0, h1, cA0, cA1, cB0, cB1;
            h0 = fmaxf(fmaxf(fmaxf(sA0_0,sA0_1),fmaxf(sA1_0,sA1_1)),
                       fmaxf(fmaxf(sA2_0,sA2_1),fmaxf(sA3_0,sA3_1)));
            h1 = fmaxf(fmaxf(fmaxf(sA0_2,sA0_3),fmaxf(sA1_2,sA1_3)),
                       fmaxf(fmaxf(sA2_2,sA2_3),fmaxf(sA3_2,sA3_3)));
            h0 = fmaxf(h0, __shfl_xor_sync(0xFFFFFFFFu, h0, 1));
            h0 = fmaxf(h0, __shfl_xor_sync(0xFFFFFFFFu, h0, 2));
            h1 = fmaxf(h1, __shfl_xor_sync(0xFFFFFFFFu, h1, 1));
            h1 = fmaxf(h1, __shfl_xor_sync(0xFFFFFFFFu, h1, 2));
            {
                float mn0 = fmaxf(mA0, h0), mn1 = fmaxf(mA1, h1);
                cA0 = fast_exp2(mA0 - mn0); cA1 = fast_exp2(mA1 - mn1);
                mA0 = mn0; mA1 = mn1;
            }
            h0 = fmaxf(fmaxf(fmaxf(sB0_0,sB0_1),fmaxf(sB1_0,sB1_1)),
                       fmaxf(fmaxf(sB2_0,sB2_1),fmaxf(sB3_0,sB3_1)));
            h1 = fmaxf(fmaxf(fmaxf(sB0_2,sB0_3),fmaxf(sB1_2,sB1_3)),
                       fmaxf(fmaxf(sB2_2,sB2_3),fmaxf(sB3_2,sB3_3)));
            h0 = fmaxf(h0, __shfl_xor_sync(0xFFFFFFFFu, h0, 1));
            h0 = fmaxf(h0, __shfl_xor_sync(0xFFFFFFFFu, h0, 2));
            h1 = fmaxf(h1, __shfl_xor_sync(0xFFFFFFFFu, h1, 1));
            h1 = fmaxf(h1, __shfl_xor_sync(0xFFFFFFFFu, h1, 2));
            {
                float mn0 = fmaxf(mB0, h0), mn1 = fmaxf(mB1, h1);
                cB0 = fast_exp2(mB0 - mn0); cB1 = fast_exp2(mB1 - mn1);
                mB0 = mn0; mB1 = mn1;
            }
#define EXPROW(S, M0, M1) S##_0 = fast_exp2(S##_0 - M0); S##_1 = fast_exp2(S##_1 - M0); \
                          S##_2 = fast_exp2(S##_2 - M1); S##_3 = fast_exp2(S##_3 - M1);
            EXPROW(sA0, mA0, mA1) EXPROW(sA1, mA0, mA1) EXPROW(sA2, mA0, mA1) EXPROW(sA3, mA0, mA1)
            EXPROW(sB0, mB0, mB1) EXPROW(sB1, mB0, mB1) EXPROW(sB2, mB0, mB1) EXPROW(sB3, mB0, mB1)
#undef EXPROW
            {
                float r0 = ((sA0_0+sA0_1)+(sA1_0+sA1_1)) + ((sA2_0+sA2_1)+(sA3_0+sA3_1));
                float r1 = ((sA0_2+sA0_3)+(sA1_2+sA1_3)) + ((sA2_2+sA2_3)+(sA3_2+sA3_3));
                r0 += __shfl_xor_sync(0xFFFFFFFFu, r0, 1);
                r0 += __shfl_xor_sync(0xFFFFFFFFu, r0, 2);
                r1 += __shfl_xor_sync(0xFFFFFFFFu, r1, 1);
                r1 += __shfl_xor_sync(0xFFFFFFFFu, r1, 2);
                lA0 = lA0 * cA0 + r0; lA1 = lA1 * cA1 + r1;
                r0 = ((sB0_0+sB0_1)+(sB1_0+sB1_1)) + ((sB2_0+sB2_1)+(sB3_0+sB3_1));
                r1 = ((sB0_2+sB0_3)+(sB1_2+sB1_3)) + ((sB2_2+sB2_3)+(sB3_2+sB3_3));
                r0 += __shfl_xor_sync(0xFFFFFFFFu, r0, 1);
                r0 += __shfl_xor_sync(0xFFFFFFFFu, r0, 2);
                r1 += __shfl_xor_sync(0xFFFFFFFFu, r1, 1);
                r1 += __shfl_xor_sync(0xFFFFFFFFu, r1, 2);
                lB0 = lB0 * cB0 + r0; lB1 = lB1 * cB1 + r1;
            }
#define OSC(M, JO) o##M##JO##_0 *= c##M##0; o##M##JO##_1 *= c##M##0; \
                   o##M##JO##_2 *= c##M##1; o##M##JO##_3 *= c##M##1;
            OSC(A,0) OSC(A,1) OSC(A,2) OSC(A,3) OSC(B,0) OSC(B,1) OSC(B,2) OSC(B,3)
#undef OSC

            unsigned pa0,pa1,pa2,pa3, pb0,pb1,pb2,pb3;
#define PV_JO(JO, VADDR) do { unsigned v0, v1; LDSMX2T(v0, v1, (VADDR));       \
            MMA(oA##JO##_0,oA##JO##_1,oA##JO##_2,oA##JO##_3, pa0,pa1,pa2,pa3, v0,v1); \
            MMA(oB##JO##_0,oB##JO##_1,oB##JO##_2,oB##JO##_3, pb0,pb1,pb2,pb3, v0,v1); \
        } while (0)
            H2(pa0, sA0_0, sA0_1); H2(pa1, sA0_2, sA0_3);
            H2(pa2, sA1_0, sA1_1); H2(pa3, sA1_2, sA1_3);
            H2(pb0, sB0_0, sB0_1); H2(pb1, sB0_2, sB0_3);
            H2(pb2, sB1_0, sB1_1); H2(pb3, sB1_2, sB1_3);
            PV_JO(0, vA + 0);  PV_JO(1, vA + 16);
            PV_JO(2, vA + 32); PV_JO(3, vA + 48);
            H2(pa0, sA2_0, sA2_1); H2(pa1, sA2_2, sA2_3);
            H2(pa2, sA3_0, sA3_1); H2(pa3, sA3_2, sA3_3);
            H2(pb0, sB2_0, sB2_1); H2(pb1, sB2_2, sB2_3);
            H2(pb2, sB3_0, sB3_1); H2(pb3, sB3_2, sB3_3);
            PV_JO(0, vA + 1280);      PV_JO(1, vA + 1280 + 16);
            PV_JO(2, vA + 1280 + 32); PV_JO(3, vA + 1280 + 48);
#undef PV_JO
        }
    }

    {
        const float iA0 = 1.f / lA0, iA1 = 1.f / lA1;
        const float iB0 = 1.f / lB0, iB1 = 1.f / lB1;
        const int qr0A = w * 32 + (l >> 2);
        const size_t gb = (size_t)n * (CC * HW);
        const int c2l = (l & 3) * 2;
#define ST_O(M, JO, QR0, I0, I1)                                               \
        {                                                                      \
            int ch0 = (JO)*8 + c2l;                                            \
            g_o[gb + (size_t)(ch0*8 + head)*256 + (QR0)]     = __float2half(o##M##JO##_0 * I0); \
            g_o[gb + (size_t)((ch0+1)*8 + head)*256 + (QR0)] = __float2half(o##M##JO##_1 * I0); \
            g_o[gb + (size_t)(ch0*8 + head)*256 + (QR0) + 8]     = __float2half(o##M##JO##_2 * I1); \
            g_o[gb + (size_t)((ch0+1)*8 + head)*256 + (QR0) + 8] = __float2half(o##M##JO##_3 * I1); \
        }
        ST_O(A,0, qr0A, iA0, iA1) ST_O(A,1, qr0A, iA0, iA1)
        ST_O(A,2, qr0A, iA0, iA1) ST_O(A,3, qr0A, iA0, iA1)
        ST_O(B,0, qr0A + 16, iB0, iB1) ST_O(B,1, qr0A + 16, iB0, iB1)
        ST_O(B,2, qr0A + 16, iB0, iB1) ST_O(B,3, qr0A + 16, iB0, iB1)
#undef ST_O
    }
}

// ---------------------------------------------------------------------------
extern "C" void kernel_launch(void* const* d_in, const int* in_sizes, int n_in,
                              void* d_out, int out_size)
{
    const float* x      = (const float*)d_in[0];
    const float* w_qkv  = (const float*)d_in[1];
    const float* b_qkv  = (const float*)d_in[2];
    const float* w_out  = (const float*)d_in[3];
    const float* b_out  = (const float*)d_in[4];
    const int*   access = (const int*)d_in[5];
    float* out = (float*)d_out;

    convert_w<<<768, 256>>>(w_qkv, w_out);
    {
        dim3 grid(NT * HW / 128, 768 / 128);   // 104 x 6
        tc_gemm<0><<<grid, 256>>>(x, b_qkv, nullptr);
    }
    attn_tc<<<NT * NHEAD, 256>>>(access);
    {
        dim3 grid(NT * HW / 128, 256 / 128);   // 104 x 2
        tc_gemm<1><<<grid, 256>>>(nullptr, b_out, out);
    }
}

// round 17
// speedup vs baseline: 7.8444x; 1.0759x over previous
#include <cuda_runtime.h>
#include <cuda_fp16.h>
#include <math.h>

// Problem constants
#define TT 26
#define NB 2
#define NT (NB*TT)      // 52 frames
#define CC 256
#define HW 256          // 16*16
#define NHEAD 8
#define CPH 32          // C / NHEAD

// fp16 caches, head-major: [((n*8+head)*256 + hw)*32 + cph]
__device__ __half g_q[(size_t)NT * NHEAD * HW * CPH];   // 6.8 MB (pre-scaled)
__device__ __half g_k[(size_t)NT * NHEAD * HW * CPH];   // 6.8 MB
__device__ __half g_v[(size_t)NT * NHEAD * HW * CPH];   // 6.8 MB
// fp16 attention output, projection layout: [n][c=cph*8+head][hw]
__device__ __half g_o[(size_t)NT * CC * HW];            // 6.8 MB
// fp16 weights
__device__ __half g_wh[768 * 256];                      // w_qkv fp16
__device__ __half g_woh[256 * 256];                     // w_out fp16

// Fast 2^x on the FMA pipe (x <= 0).
__device__ __forceinline__ float fast_exp2(float x) {
    float y = fmaxf(x, -126.0f);
    float fn = y + 12582912.0f;
    int n = __float_as_int(fn) - 0x4B400000;
    float r = y - (fn - 12582912.0f);
    float p = 1.3333558146e-3f;
    p = fmaf(p, r, 9.6181291794e-3f);
    p = fmaf(p, r, 5.5504108664e-2f);
    p = fmaf(p, r, 2.4022650696e-1f);
    p = fmaf(p, r, 6.9314718056e-1f);
    p = fmaf(p, r, 1.0f);
    return p * __int_as_float((n + 127) << 23);
}

// ---- PTX wrappers -------------------------------------------------------
#define LDSMX2(R0, R1, ADDR) \
    asm volatile("ldmatrix.sync.aligned.m8n8.x2.shared.b16 {%0,%1},[%2];" \
                 : "=r"(R0), "=r"(R1) : "r"(ADDR))
#define LDSMX2T(R0, R1, ADDR) \
    asm volatile("ldmatrix.sync.aligned.m8n8.x2.trans.shared.b16 {%0,%1},[%2];" \
                 : "=r"(R0), "=r"(R1) : "r"(ADDR))
#define LDSMX4(R0, R1, R2, R3, ADDR) \
    asm volatile("ldmatrix.sync.aligned.m8n8.x4.shared.b16 {%0,%1,%2,%3},[%4];" \
                 : "=r"(R0), "=r"(R1), "=r"(R2), "=r"(R3) : "r"(ADDR))
#define MMA(C0, C1, C2, C3, A0, A1, A2, A3, B0, B1) \
    asm volatile("mma.sync.aligned.m16n8k16.row.col.f32.f16.f16.f32 " \
                 "{%0,%1,%2,%3},{%4,%5,%6,%7},{%8,%9},{%0,%1,%2,%3};" \
                 : "+f"(C0), "+f"(C1), "+f"(C2), "+f"(C3) \
                 : "r"(A0), "r"(A1), "r"(A2), "r"(A3), "r"(B0), "r"(B1))
#define H2(U, LO, HI) \
    asm("cvt.rn.f16x2.f32 %0,%1,%2;" : "=r"(U) : "f"(HI), "f"(LO))

// ---------------------------------------------------------------------------
// convert_w: fp32 weights -> fp16 copies.
// ---------------------------------------------------------------------------
__global__ __launch_bounds__(256, 1)
void convert_w(const float* __restrict__ w_qkv, const float* __restrict__ w_out)
{
    int i = blockIdx.x * 256 + threadIdx.x;
    if (i < 768 * 256) g_wh[i] = __float2half(w_qkv[i]);
    if (i < 256 * 256) g_woh[i] = __float2half(w_out[i]);
}

// ---------------------------------------------------------------------------
// tc_gemm<MODE>: fp16 tensor-core GEMM, 128x128 block tile, K-chunk 32,
// 8 warps (warp tile 32m x 64n), DOUBLE-BUFFERED software pipeline:
// iteration = { issue next tile's global loads -> regs | MMA on cur buffer |
//               store regs -> other buffer | one sync }.
// MODE 0 (qkv): A = x fp32 (convert on stage), N=768 -> g_q/g_k/g_v.
// MODE 1 (out): A = g_o fp16, N=256 -> fp32 +bias to out.
// ---------------------------------------------------------------------------
template <int MODE>
__global__ __launch_bounds__(256, 1)
void tc_gemm(const float* __restrict__ xA,
             const float* __restrict__ bias,
             float* __restrict__ out)
{
    __shared__ __align__(16) __half smA[2][128 * 40];   // pitch 80 B, 10240 B/buf
    __shared__ __align__(16) __half smB[2][128 * 40];

    const int tid = threadIdx.x;
    const int w   = tid >> 5;
    const int l   = tid & 31;
    const int wm  = w & 3;
    const int wn  = w >> 2;

    const int m0  = blockIdx.x * 128;
    const int nn  = m0 >> 8;
    const int hwb = m0 & 255;
    const int o0  = blockIdx.y * 128;

    unsigned As_u, Bs_u;
    asm("{ .reg .u64 t0; cvta.to.shared.u64 t0, %1; cvt.u32.u64 %0, t0; }"
        : "=r"(As_u) : "l"(smA));
    asm("{ .reg .u64 t0; cvta.to.shared.u64 t0, %1; cvt.u32.u64 %0, t0; }"
        : "=r"(Bs_u) : "l"(smB));

    const int sm_m = tid & 127;
    const int sg   = tid >> 7;
    const __half* Wh = (MODE == 0) ? g_wh : g_woh;
    const float*  Af = xA + (size_t)nn * CC * HW + hwb;
    const __half* Ah = g_o + (size_t)nn * CC * HW + hwb;

    const int bln  = tid >> 1;            // B row 0..127 (2 threads/row)
    const int blc  = (tid & 1) * 16;      // halves offset 0/16
    const __half* Bg = Wh + (size_t)(o0 + bln) * 256 + blc;

    const unsigned a_lane = As_u + (wm * 32 + (l & 15)) * 80 + (l >> 4) * 16;
    const unsigned b_lane = Bs_u + (wn * 64 + (l & 7)) * 80 + ((l >> 3) & 1) * 16;

#define FOR_NT(F) F(0) F(1) F(2) F(3) F(4) F(5) F(6) F(7)
#define DEF_ACC(NT) float c0##NT##_0=0.f,c0##NT##_1=0.f,c0##NT##_2=0.f,c0##NT##_3=0.f, \
                          c1##NT##_0=0.f,c1##NT##_1=0.f,c1##NT##_2=0.f,c1##NT##_3=0.f;
    FOR_NT(DEF_ACC)
#undef DEF_ACC

    // staging registers
    unsigned aR0,aR1,aR2,aR3,aR4,aR5,aR6,aR7;
    uint4 bR0, bR1;

#define LOAD_REGS(K0) do {                                                     \
        if (MODE == 0) {                                                       \
            float x0, x1;                                                      \
            x0 = Af[(size_t)((K0) + sg*16 + 0) * HW + sm_m];                   \
            x1 = Af[(size_t)((K0) + sg*16 + 1) * HW + sm_m]; H2(aR0, x0, x1);  \
            x0 = Af[(size_t)((K0) + sg*16 + 2) * HW + sm_m];                   \
            x1 = Af[(size_t)((K0) + sg*16 + 3) * HW + sm_m]; H2(aR1, x0, x1);  \
            x0 = Af[(size_t)((K0) + sg*16 + 4) * HW + sm_m];                   \
            x1 = Af[(size_t)((K0) + sg*16 + 5) * HW + sm_m]; H2(aR2, x0, x1);  \
            x0 = Af[(size_t)((K0) + sg*16 + 6) * HW + sm_m];                   \
            x1 = Af[(size_t)((K0) + sg*16 + 7) * HW + sm_m]; H2(aR3, x0, x1);  \
            x0 = Af[(size_t)((K0) + sg*16 + 8) * HW + sm_m];                   \
            x1 = Af[(size_t)((K0) + sg*16 + 9) * HW + sm_m]; H2(aR4, x0, x1);  \
            x0 = Af[(size_t)((K0) + sg*16 +10) * HW + sm_m];                   \
            x1 = Af[(size_t)((K0) + sg*16 +11) * HW + sm_m]; H2(aR5, x0, x1);  \
            x0 = Af[(size_t)((K0) + sg*16 +12) * HW + sm_m];                   \
            x1 = Af[(size_t)((K0) + sg*16 +13) * HW + sm_m]; H2(aR6, x0, x1);  \
            x0 = Af[(size_t)((K0) + sg*16 +14) * HW + sm_m];                   \
            x1 = Af[(size_t)((K0) + sg*16 +15) * HW + sm_m]; H2(aR7, x0, x1);  \
        } else {                                                               \
            aR0 = (unsigned)__half_as_ushort(Ah[(size_t)((K0)+sg*16+0)*HW+sm_m]) \
                | ((unsigned)__half_as_ushort(Ah[(size_t)((K0)+sg*16+1)*HW+sm_m]) << 16); \
            aR1 = (unsigned)__half_as_ushort(Ah[(size_t)((K0)+sg*16+2)*HW+sm_m]) \
                | ((unsigned)__half_as_ushort(Ah[(size_t)((K0)+sg*16+3)*HW+sm_m]) << 16); \
            aR2 = (unsigned)__half_as_ushort(Ah[(size_t)((K0)+sg*16+4)*HW+sm_m]) \
                | ((unsigned)__half_as_ushort(Ah[(size_t)((K0)+sg*16+5)*HW+sm_m]) << 16); \
            aR3 = (unsigned)__half_as_ushort(Ah[(size_t)((K0)+sg*16+6)*HW+sm_m]) \
                | ((unsigned)__half_as_ushort(Ah[(size_t)((K0)+sg*16+7)*HW+sm_m]) << 16); \
            aR4 = (unsigned)__half_as_ushort(Ah[(size_t)((K0)+sg*16+8)*HW+sm_m]) \
                | ((unsigned)__half_as_ushort(Ah[(size_t)((K0)+sg*16+9)*HW+sm_m]) << 16); \
            aR5 = (unsigned)__half_as_ushort(Ah[(size_t)((K0)+sg*16+10)*HW+sm_m]) \
                | ((unsigned)__half_as_ushort(Ah[(size_t)((K0)+sg*16+11)*HW+sm_m]) << 16); \
            aR6 = (unsigned)__half_as_ushort(Ah[(size_t)((K0)+sg*16+12)*HW+sm_m]) \
                | ((unsigned)__half_as_ushort(Ah[(size_t)((K0)+sg*16+13)*HW+sm_m]) << 16); \
            aR7 = (unsigned)__half_as_ushort(Ah[(size_t)((K0)+sg*16+14)*HW+sm_m]) \
                | ((unsigned)__half_as_ushort(Ah[(size_t)((K0)+sg*16+15)*HW+sm_m]) << 16); \
        }                                                                      \
        bR0 = *(const uint4*)(Bg + (K0));                                      \
        bR1 = *(const uint4*)(Bg + (K0) + 8);                                  \
    } while (0)

#define STORE_SMEM(BUF) do {                                                   \
        char* ab = (char*)smA + (BUF) * 10240 + sm_m * 80 + sg * 32;           \
        *(unsigned*)(ab + 0)  = aR0; *(unsigned*)(ab + 4)  = aR1;              \
        *(unsigned*)(ab + 8)  = aR2; *(unsigned*)(ab + 12) = aR3;              \
        *(unsigned*)(ab + 16) = aR4; *(unsigned*)(ab + 20) = aR5;              \
        *(unsigned*)(ab + 24) = aR6; *(unsigned*)(ab + 28) = aR7;              \
        char* bb = (char*)smB + (BUF) * 10240 + bln * 80 + blc * 2;            \
        *(uint4*)(bb + 0)  = bR0;                                              \
        *(uint4*)(bb + 16) = bR1;                                              \
    } while (0)

    LOAD_REGS(0);
    STORE_SMEM(0);
    __syncthreads();

    for (int kc = 0; kc < 8; kc++) {
        const unsigned cb = (kc & 1) * 10240;
        if (kc < 7) LOAD_REGS((kc + 1) * 32);

#pragma unroll
        for (int ks = 0; ks < 2; ks++) {
            unsigned a00,a01,a02,a03, a10,a11,a12,a13;
            LDSMX4(a00,a01,a02,a03, a_lane + cb + ks * 32);
            LDSMX4(a10,a11,a12,a13, a_lane + cb + 1280 + ks * 32);
#define DO_NT(NT) { unsigned b0, b1; \
            LDSMX2(b0, b1, b_lane + cb + (NT) * 640 + ks * 32); \
            MMA(c0##NT##_0,c0##NT##_1,c0##NT##_2,c0##NT##_3, a00,a01,a02,a03, b0,b1); \
            MMA(c1##NT##_0,c1##NT##_1,c1##NT##_2,c1##NT##_3, a10,a11,a12,a13, b0,b1); }
            FOR_NT(DO_NT)
#undef DO_NT
        }

        if (kc < 7) STORE_SMEM((kc + 1) & 1);
        __syncthreads();
    }
#undef LOAD_REGS
#undef STORE_SMEM

    // ---- epilogue ----
    const int ocb = o0 + wn * 64 + (l & 3) * 2;
    const int rb  = hwb + wm * 32 + (l >> 2);

    if (MODE == 0) {
        const float qscale = 0.17677669529663687f * 1.4426950408889634f;
#define ST1(V, OC, HWV) { \
        int o_ = (OC); float bb = bias[o_]; int part = o_ >> 8; int ci = o_ & 255; \
        __half* dst = (part == 0) ? g_q : ((part == 1) ? g_k : g_v); \
        float sc = (part == 0) ? qscale : 1.0f; \
        dst[(((size_t)nn * 8 + (ci & 7)) * 256 + (HWV)) * 32 + (ci >> 3)] = \
            __float2half(((V) + bb) * sc); }
#define EPI0(NT) \
        ST1(c0##NT##_0, ocb + (NT)*8,     rb) \
        ST1(c0##NT##_1, ocb + (NT)*8 + 1, rb) \
        ST1(c0##NT##_2, ocb + (NT)*8,     rb + 8) \
        ST1(c0##NT##_3, ocb + (NT)*8 + 1, rb + 8) \
        ST1(c1##NT##_0, ocb + (NT)*8,     rb + 16) \
        ST1(c1##NT##_1, ocb + (NT)*8 + 1, rb + 16) \
        ST1(c1##NT##_2, ocb + (NT)*8,     rb + 24) \
        ST1(c1##NT##_3, ocb + (NT)*8 + 1, rb + 24)
        FOR_NT(EPI0)
#undef EPI0
#undef ST1
    } else {
#define ST1B(V, OC, HWV) \
        out[((size_t)nn * CC + (OC)) * HW + (HWV)] = (V) + bias[(OC)];
#define EPI1(NT) \
        ST1B(c0##NT##_0, ocb + (NT)*8,     rb) \
        ST1B(c0##NT##_1, ocb + (NT)*8 + 1, rb) \
        ST1B(c0##NT##_2, ocb + (NT)*8,     rb + 8) \
        ST1B(c0##NT##_3, ocb + (NT)*8 + 1, rb + 8) \
        ST1B(c1##NT##_0, ocb + (NT)*8,     rb + 16) \
        ST1B(c1##NT##_1, ocb + (NT)*8 + 1, rb + 16) \
        ST1B(c1##NT##_2, ocb + (NT)*8,     rb + 24) \
        ST1B(c1##NT##_3, ocb + (NT)*8 + 1, rb + 24)
        FOR_NT(EPI1)
#undef EPI1
#undef ST1B
    }
#undef FOR_NT
}

// ---------------------------------------------------------------------------
// Tensor-core flash attention, double-buffered K/V pipeline.
// Q staging region (dead after fragment load) is reused as buffer 1.
// Buffers: bufK(i) = sbase + i*20480 B, bufV(i) = bufK(i) + 10240 B.
// ---------------------------------------------------------------------------
__global__ __launch_bounds__(256, 1)
void attn_tc(const int* __restrict__ access)
{
    __shared__ __align__(16) __half sm_h[20480];       // 40960 B

    const int tid  = threadIdx.x;
    const int w    = tid >> 5;
    const int l    = tid & 31;
    const int bid  = blockIdx.x;
    const int n    = bid >> 3;
    const int head = bid & 7;
    const int t    = n % TT;
    const int b_   = n / TT;

    unsigned sbase;
    asm("{ .reg .u64 t0; cvta.to.shared.u64 t0, %1; cvt.u32.u64 %0, t0; }"
        : "=r"(sbase) : "l"(sm_h));

    // ---- Load Q tile (256 rows x 32 halves = 1024 uint4; 4 per thread) ----
    {
        const size_t qbase = ((size_t)n * 8 + head) * (size_t)(HW * CPH);
#pragma unroll
        for (int u = 0; u < 4; u++) {
            int lin = tid * 4 + u;
            int row = lin >> 2, cb16 = (lin & 3) * 16;
            uint4 rq = *((const uint4*)(g_q + qbase) + lin);
            *(uint4*)((char*)sm_h + row * 80 + cb16) = rq;
        }
    }
    __syncthreads();

    unsigned aqA0_0,aqA0_1,aqA0_2,aqA0_3, aqA1_0,aqA1_1,aqA1_2,aqA1_3;
    unsigned aqB0_0,aqB0_1,aqB0_2,aqB0_3, aqB1_0,aqB1_1,aqB1_2,aqB1_3;
    {
        unsigned qrow = sbase + (w * 32 + (l & 15)) * 80 + (l >> 4) * 16;
        LDSMX4(aqA0_0,aqA0_1,aqA0_2,aqA0_3, qrow);
        LDSMX4(aqA1_0,aqA1_1,aqA1_2,aqA1_3, qrow + 32);
        LDSMX4(aqB0_0,aqB0_1,aqB0_2,aqB0_3, qrow + 16*80);
        LDSMX4(aqB1_0,aqB1_1,aqB1_2,aqB1_3, qrow + 16*80 + 32);
    }
    __syncthreads();   // Q smem region now dead -> reusable as KV buffer 1

    const unsigned k_rel = (l & 7) * 80 + ((l >> 3) & 1) * 16;
    const unsigned v_rel = (l & 15) * 80;
    const int st_row  = (tid * 2) >> 2;          // staging row (2 uint4/thread)
    const int st_cb0  = ((tid * 2) & 3) * 16;
    const int st_cb1  = ((tid * 2 + 1) & 3) * 16;

    float mA0 = -1e30f, mA1 = -1e30f, mB0 = -1e30f, mB1 = -1e30f;
    float lA0 = 0.f, lA1 = 0.f, lB0 = 0.f, lB1 = 0.f;
    float oA0_0=0.f,oA0_1=0.f,oA0_2=0.f,oA0_3=0.f, oA1_0=0.f,oA1_1=0.f,oA1_2=0.f,oA1_3=0.f;
    float oA2_0=0.f,oA2_1=0.f,oA2_2=0.f,oA2_3=0.f, oA3_0=0.f,oA3_1=0.f,oA3_2=0.f,oA3_3=0.f;
    float oB0_0=0.f,oB0_1=0.f,oB0_2=0.f,oB0_3=0.f, oB1_0=0.f,oB1_1=0.f,oB1_2=0.f,oB1_3=0.f;
    float oB2_0=0.f,oB2_1=0.f,oB2_2=0.f,oB2_3=0.f, oB3_0=0.f,oB3_1=0.f,oB3_2=0.f,oB3_3=0.f;

    uint4 kR0, kR1, vR0, vR1;

#define LOAD_KV(TTI) do {                                                      \
        int f_ = access[t * 4 + ((TTI) >> 1)];                                 \
        size_t kb_ = (((size_t)(b_ * TT + f_) * 8 + head) * 256                \
                     + ((TTI) & 1) * 128) * 32;                                \
        kR0 = *((const uint4*)(g_k + kb_) + tid * 2);                          \
        kR1 = *((const uint4*)(g_k + kb_) + tid * 2 + 1);                      \
        vR0 = *((const uint4*)(g_v + kb_) + tid * 2);                          \
        vR1 = *((const uint4*)(g_v + kb_) + tid * 2 + 1);                      \
    } while (0)

#define STORE_KV(BUF) do {                                                     \
        char* kb = (char*)sm_h + (BUF) * 20480;                                \
        *(uint4*)(kb + st_row * 80 + st_cb0) = kR0;                            \
        *(uint4*)(kb + st_row * 80 + st_cb1) = kR1;                            \
        *(uint4*)(kb + 10240 + st_row * 80 + st_cb0) = vR0;                    \
        *(uint4*)(kb + 10240 + st_row * 80 + st_cb1) = vR1;                    \
    } while (0)

    LOAD_KV(0);
    STORE_KV(0);
    __syncthreads();

    for (int tt = 0; tt < 8; tt++) {
        const unsigned bufb = sbase + (tt & 1) * 20480;
        if (tt < 7) LOAD_KV(tt + 1);

#pragma unroll
        for (int cc = 0; cc < 4; cc++) {
            const int c32 = cc * 32;
            const unsigned kA = bufb + k_rel + c32 * 80;
            const unsigned vA = bufb + 10240 + v_rel + c32 * 80;

            float sA0_0=0.f,sA0_1=0.f,sA0_2=0.f,sA0_3=0.f, sA1_0=0.f,sA1_1=0.f,sA1_2=0.f,sA1_3=0.f;
            float sA2_0=0.f,sA2_1=0.f,sA2_2=0.f,sA2_3=0.f, sA3_0=0.f,sA3_1=0.f,sA3_2=0.f,sA3_3=0.f;
            float sB0_0=0.f,sB0_1=0.f,sB0_2=0.f,sB0_3=0.f, sB1_0=0.f,sB1_1=0.f,sB1_2=0.f,sB1_3=0.f;
            float sB2_0=0.f,sB2_1=0.f,sB2_2=0.f,sB2_3=0.f, sB3_0=0.f,sB3_1=0.f,sB3_2=0.f,sB3_3=0.f;

#define QK_NT(J) do { unsigned b0,b1,b2,b3;                                    \
            LDSMX2(b0, b1, kA + (J)*640);                                      \
            LDSMX2(b2, b3, kA + (J)*640 + 32);                                 \
            MMA(sA##J##_0,sA##J##_1,sA##J##_2,sA##J##_3, aqA0_0,aqA0_1,aqA0_2,aqA0_3, b0,b1); \
            MMA(sA##J##_0,sA##J##_1,sA##J##_2,sA##J##_3, aqA1_0,aqA1_1,aqA1_2,aqA1_3, b2,b3); \
            MMA(sB##J##_0,sB##J##_1,sB##J##_2,sB##J##_3, aqB0_0,aqB0_1,aqB0_2,aqB0_3, b0,b1); \
            MMA(sB##J##_0,sB##J##_1,sB##J##_2,sB##J##_3, aqB1_0,aqB1_1,aqB1_2,aqB1_3, b2,b3); \
        } while (0)
            QK_NT(0); QK_NT(1); QK_NT(2); QK_NT(3);
#undef QK_NT

            float h0, h1, cA0, cA1, cB0, cB1;
            h0 = fmaxf(fmaxf(fmaxf(sA0_0,sA0_1),fmaxf(sA1_0,sA1_1)),
                       fmaxf(fmaxf(sA2_0,sA2_1),fmaxf(sA3_0,sA3_1)));
            h1 = fmaxf(fmaxf(fmaxf(sA0_2,sA0_3),fmaxf(sA1_2,sA1_3)),
                       fmaxf(fmaxf(sA2_2,sA2_3),fmaxf(sA3_2,sA3_3)));
            h0 = fmaxf(h0, __shfl_xor_sync(0xFFFFFFFFu, h0, 1));
            h0 = fmaxf(h0, __shfl_xor_sync(0xFFFFFFFFu, h0, 2));
            h1 = fmaxf(h1, __shfl_xor_sync(0xFFFFFFFFu, h1, 1));
            h1 = fmaxf(h1, __shfl_xor_sync(0xFFFFFFFFu, h1, 2));
            {
                float mn0 = fmaxf(mA0, h0), mn1 = fmaxf(mA1, h1);
                cA0 = fast_exp2(mA0 - mn0); cA1 = fast_exp2(mA1 - mn1);
                mA0 = mn0; mA1 = mn1;
            }
            h0 = fmaxf(fmaxf(fmaxf(sB0_0,sB0_1),fmaxf(sB1_0,sB1_1)),
                       fmaxf(fmaxf(sB2_0,sB2_1),fmaxf(sB3_0,sB3_1)));
            h1 = fmaxf(fmaxf(fmaxf(sB0_2,sB0_3),fmaxf(sB1_2,sB1_3)),
                       fmaxf(fmaxf(sB2_2,sB2_3),fmaxf(sB3_2,sB3_3)));
            h0 = fmaxf(h0, __shfl_xor_sync(0xFFFFFFFFu, h0, 1));
            h0 = fmaxf(h0, __shfl_xor_sync(0xFFFFFFFFu, h0, 2));
            h1 = fmaxf(h1, __shfl_xor_sync(0xFFFFFFFFu, h1, 1));
            h1 = fmaxf(h1, __shfl_xor_sync(0xFFFFFFFFu, h1, 2));
            {
                float mn0 = fmaxf(mB0, h0), mn1 = fmaxf(mB1, h1);
                cB0 = fast_exp2(mB0 - mn0); cB1 = fast_exp2(mB1 - mn1);
                mB0 = mn0; mB1 = mn1;
            }
#define EXPROW(S, M0, M1) S##_0 = fast_exp2(S##_0 - M0); S##_1 = fast_exp2(S##_1 - M0); \
                          S##_2 = fast_exp2(S##_2 - M1); S##_3 = fast_exp2(S##_3 - M1);
            EXPROW(sA0, mA0, mA1) EXPROW(sA1, mA0, mA1) EXPROW(sA2, mA0, mA1) EXPROW(sA3, mA0, mA1)
            EXPROW(sB0, mB0, mB1) EXPROW(sB1, mB0, mB1) EXPROW(sB2, mB0, mB1) EXPROW(sB3, mB0, mB1)
#undef EXPROW
            {
                float r0 = ((sA0_0+sA0_1)+(sA1_0+sA1_1)) + ((sA2_0+sA2_1)+(sA3_0+sA3_1));
                float r1 = ((sA0_2+sA0_3)+(sA1_2+sA1_3)) + ((sA2_2+sA2_3)+(sA3_2+sA3_3));
                r0 += __shfl_xor_sync(0xFFFFFFFFu, r0, 1);
                r0 += __shfl_xor_sync(0xFFFFFFFFu, r0, 2);
                r1 += __shfl_xor_sync(0xFFFFFFFFu, r1, 1);
                r1 += __shfl_xor_sync(0xFFFFFFFFu, r1, 2);
                lA0 = lA0 * cA0 + r0; lA1 = lA1 * cA1 + r1;
                r0 = ((sB0_0+sB0_1)+(sB1_0+sB1_1)) + ((sB2_0+sB2_1)+(sB3_0+sB3_1));
                r1 = ((sB0_2+sB0_3)+(sB1_2+sB1_3)) + ((sB2_2+sB2_3)+(sB3_2+sB3_3));
                r0 += __shfl_xor_sync(0xFFFFFFFFu, r0, 1);
                r0 += __shfl_xor_sync(0xFFFFFFFFu, r0, 2);
                r1 += __shfl_xor_sync(0xFFFFFFFFu, r1, 1);
                r1 += __shfl_xor_sync(0xFFFFFFFFu, r1, 2);
                lB0 = lB0 * cB0 + r0; lB1 = lB1 * cB1 + r1;
            }
#define OSC(M, JO) o##M##JO##_0 *= c##M##0; o##M##JO##_1 *= c##M##0; \
                   o##M##JO##_2 *= c##M##1; o##M##JO##_3 *= c##M##1;
            OSC(A,0) OSC(A,1) OSC(A,2) OSC(A,3) OSC(B,0) OSC(B,1) OSC(B,2) OSC(B,3)
#undef OSC

            unsigned pa0,pa1,pa2,pa3, pb0,pb1,pb2,pb3;
#define PV_JO(JO, VADDR) do { unsigned v0, v1; LDSMX2T(v0, v1, (VADDR));       \
            MMA(oA##JO##_0,oA##JO##_1,oA##JO##_2,oA##JO##_3, pa0,pa1,pa2,pa3, v0,v1); \
            MMA(oB##JO##_0,oB##JO##_1,oB##JO##_2,oB##JO##_3, pb0,pb1,pb2,pb3, v0,v1); \
        } while (0)
            H2(pa0, sA0_0, sA0_1); H2(pa1, sA0_2, sA0_3);
            H2(pa2, sA1_0, sA1_1); H2(pa3, sA1_2, sA1_3);
            H2(pb0, sB0_0, sB0_1); H2(pb1, sB0_2, sB0_3);
            H2(pb2, sB1_0, sB1_1); H2(pb3, sB1_2, sB1_3);
            PV_JO(0, vA + 0);  PV_JO(1, vA + 16);
            PV_JO(2, vA + 32); PV_JO(3, vA + 48);
            H2(pa0, sA2_0, sA2_1); H2(pa1, sA2_2, sA2_3);
            H2(pa2, sA3_0, sA3_1); H2(pa3, sA3_2, sA3_3);
            H2(pb0, sB2_0, sB2_1); H2(pb1, sB2_2, sB2_3);
            H2(pb2, sB3_0, sB3_1); H2(pb3, sB3_2, sB3_3);
            PV_JO(0, vA + 1280);      PV_JO(1, vA + 1280 + 16);
            PV_JO(2, vA + 1280 + 32); PV_JO(3, vA + 1280 + 48);
#undef PV_JO
        }

        if (tt < 7) STORE_KV((tt + 1) & 1);
        __syncthreads();
    }
#undef LOAD_KV
#undef STORE_KV

    // ---- normalize + store o (fp16) ----
    {
        const float iA0 = 1.f / lA0, iA1 = 1.f / lA1;
        const float iB0 = 1.f / lB0, iB1 = 1.f / lB1;
        const int qr0A = w * 32 + (l >> 2);
        const size_t gb = (size_t)n * (CC * HW);
        const int c2l = (l & 3) * 2;
#define ST_O(M, JO, QR0, I0, I1)                                               \
        {                                                                      \
            int ch0 = (JO)*8 + c2l;                                            \
            g_o[gb + (size_t)(ch0*8 + head)*256 + (QR0)]     = __float2half(o##M##JO##_0 * I0); \
            g_o[gb + (size_t)((ch0+1)*8 + head)*256 + (QR0)] = __float2half(o##M##JO##_1 * I0); \
            g_o[gb + (size_t)(ch0*8 + head)*256 + (QR0) + 8]     = __float2half(o##M##JO##_2 * I1); \
            g_o[gb + (size_t)((ch0+1)*8 + head)*256 + (QR0) + 8] = __float2half(o##M##JO##_3 * I1); \
        }
        ST_O(A,0, qr0A, iA0, iA1) ST_O(A,1, qr0A, iA0, iA1)
        ST_O(A,2, qr0A, iA0, iA1) ST_O(A,3, qr0A, iA0, iA1)
        ST_O(B,0, qr0A + 16, iB0, iB1) ST_O(B,1, qr0A + 16, iB0, iB1)
        ST_O(B,2, qr0A + 16, iB0, iB1) ST_O(B,3, qr0A + 16, iB0, iB1)
#undef ST_O
    }
}

// ---------------------------------------------------------------------------
extern "C" void kernel_launch(void* const* d_in, const int* in_sizes, int n_in,
                              void* d_out, int out_size)
{
    const float* x      = (const float*)d_in[0];
    const float* w_qkv  = (const float*)d_in[1];
    const float* b_qkv  = (const float*)d_in[2];
    const float* w_out  = (const float*)d_in[3];
    const float* b_out  = (const float*)d_in[4];
    const int*   access = (const int*)d_in[5];
    float* out = (float*)d_out;

    convert_w<<<768, 256>>>(w_qkv, w_out);
    {
        dim3 grid(NT * HW / 128, 768 / 128);   // 104 x 6
        tc_gemm<0><<<grid, 256>>>(x, b_qkv, nullptr);
    }
    attn_tc<<<NT * NHEAD, 256>>>(access);
    {
        dim3 grid(NT * HW / 128, 256 / 128);   // 104 x 2
        tc_gemm<1><<<grid, 256>>>(nullptr, b_out, out);
    }
}